// round 13
// baseline (speedup 1.0000x reference)
#include <cuda_runtime.h>
#include <cuda_bf16.h>
#include <cstdint>
#include <math.h>

#define B_    4
#define C_    256
#define D_    128
#define NPOS  6272
#define BN    64
#define NSPLIT 3
#define MFIX  80.0f

// ---------------- scratch (static __device__, no allocation) ----------------
__device__ __nv_bfloat16 g_xh[(size_t)B_ * C_ * NPOS];
__device__ __nv_bfloat16 g_xl[(size_t)B_ * C_ * NPOS];
__device__ __nv_bfloat16 g_wh[3 * D_ * C_];
__device__ __nv_bfloat16 g_wl[3 * D_ * C_];
__device__ __nv_bfloat16 g_qh[(size_t)B_ * NPOS * D_];
__device__ __nv_bfloat16 g_ql[(size_t)B_ * NPOS * D_];
__device__ __nv_bfloat16 g_kh[(size_t)B_ * NPOS * D_];
__device__ __nv_bfloat16 g_kl[(size_t)B_ * NPOS * D_];
__device__ __nv_bfloat16 g_vth[(size_t)B_ * D_ * NPOS];  // V^T [b][d][n]
__device__ __nv_bfloat16 g_vtl[(size_t)B_ * D_ * NPOS];
__device__ float g_yp[NSPLIT][(size_t)B_ * NPOS * D_];   // unnormalized partial O
__device__ float g_lp[NSPLIT][(size_t)B_ * NPOS];        // partial l

// ======================= helpers ==================
__device__ __forceinline__ uint32_t smem_to_u32(const void* p) {
    uint32_t a;
    asm("{ .reg .u64 t; cvta.to.shared.u64 t, %1; cvt.u32.u64 %0, t; }" : "=r"(a) : "l"(p));
    return a;
}
__device__ __forceinline__ void cpa16(uint32_t s, const void* g) {
    asm volatile("cp.async.cg.shared.global [%0], [%1], 16;" :: "r"(s), "l"(g));
}
#define CP_COMMIT() asm volatile("cp.async.commit_group;" ::: "memory")

// D = A(16x16 bf16, row) * B(16x8 bf16, col) + D (f32)
#define MMA16816(c, a, b0_, b1_) \
    asm volatile("mma.sync.aligned.m16n8k16.row.col.f32.bf16.bf16.f32 " \
        "{%0,%1,%2,%3}, {%4,%5,%6,%7}, {%8,%9}, {%0,%1,%2,%3};" \
        : "+f"((c)[0]), "+f"((c)[1]), "+f"((c)[2]), "+f"((c)[3]) \
        : "r"((a)[0]), "r"((a)[1]), "r"((a)[2]), "r"((a)[3]), "r"(b0_), "r"(b1_))

#define LDMX4(rr, addr) \
    asm volatile("ldmatrix.sync.aligned.m8n8.x4.shared.b16 {%0,%1,%2,%3}, [%4];" \
        : "=r"((rr)[0]), "=r"((rr)[1]), "=r"((rr)[2]), "=r"((rr)[3]) : "r"(addr))
#define LDMX4T(rr, addr) \
    asm volatile("ldmatrix.sync.aligned.m8n8.x4.trans.shared.b16 {%0,%1,%2,%3}, [%4];" \
        : "=r"((rr)[0]), "=r"((rr)[1]), "=r"((rr)[2]), "=r"((rr)[3]) : "r"(addr))

// split f32 pair -> hi(trunc) packed bf16x2 (a in low half) + lo(rn) packed
__device__ __forceinline__ uint32_t packsplit(float a, float b, uint32_t& lo) {
    uint32_t ua = __float_as_uint(a), ub = __float_as_uint(b);
    float r0 = a - __uint_as_float(ua & 0xFFFF0000u);
    float r1 = b - __uint_as_float(ub & 0xFFFF0000u);
    asm("cvt.rn.bf16x2.f32 %0, %1, %2;" : "=r"(lo) : "f"(r1), "f"(r0));
    return (ua >> 16) | (ub & 0xFFFF0000u);
}

// trunc-pack only, and return the truncated hi values as floats (for l = Σph)
__device__ __forceinline__ uint32_t packtrunc(float a, float b, float& ha, float& hb) {
    uint32_t ua = __float_as_uint(a), ub = __float_as_uint(b);
    ha = __uint_as_float(ua & 0xFFFF0000u);
    hb = __uint_as_float(ub & 0xFFFF0000u);
    return (ua >> 16) | (ub & 0xFFFF0000u);
}

// =============================================================================
// Kernel 0a: split x -> bf16 hi/lo.
// =============================================================================
__global__ void __launch_bounds__(256) split_x_kernel(const float* __restrict__ x)
{
    size_t i = ((size_t)blockIdx.x * 256 + threadIdx.x) * 4;
    float4 v = *(const float4*)(x + i);
    uint32_t l0, l1;
    uint32_t h0 = packsplit(v.x, v.y, l0);
    uint32_t h1 = packsplit(v.z, v.w, l1);
    *(uint2*)((uint16_t*)g_xh + i) = make_uint2(h0, h1);
    *(uint2*)((uint16_t*)g_xl + i) = make_uint2(l0, l1);
}

// Kernel 0b: split W{theta,phi,g} -> bf16 hi/lo.
__global__ void __launch_bounds__(256) split_w_kernel(
    const float* __restrict__ Wt, const float* __restrict__ Wp,
    const float* __restrict__ Wg_)
{
    int which = blockIdx.y;
    const float* W = (which == 0) ? Wt : (which == 1) ? Wp : Wg_;
    size_t i = ((size_t)blockIdx.x * 256 + threadIdx.x) * 4;
    float4 v = *(const float4*)(W + i);
    uint32_t l0, l1;
    uint32_t h0 = packsplit(v.x, v.y, l0);
    uint32_t h1 = packsplit(v.z, v.w, l1);
    size_t o = (size_t)which * (D_ * C_) + i;
    *(uint2*)((uint16_t*)g_wh + o) = make_uint2(h0, h1);
    *(uint2*)((uint16_t*)g_wl + o) = make_uint2(l0, l1);
}

// =============================================================================
// Kernel 1: proj via mma.sync (3-pass bf16 emulation), k-chunk 64 (4 iters).
// grid (49, 3, B), 256 thr.  which: 0=theta->Q, 1=phi->K, 2=g->V^T.
// SMEM stage: XH [64][136 bf16] 17408 | XL 17408 | WH [128][72] 18432 | WL 18432
// =============================================================================
#define PSTG 71680
#define PROJ_SMEM (3 * PSTG)   // 215040
#define P_XL 17408
#define P_WH 34816
#define P_WL 53248

__device__ __forceinline__ void proj_ld(uint32_t sb, int s, int b, int which,
                                        int c0, int n0, int tid)
{
    uint32_t st = sb + (uint32_t)s * PSTG;
#pragma unroll
    for (int i = 0; i < 4; i++) {
        int ch = tid + i * 256;
        int r = ch >> 4, c16 = ch & 15;
        size_t src = ((size_t)(b * C_ + c0 + r)) * NPOS + n0 + c16 * 8;
        uint32_t dst = (uint32_t)(r * 272 + c16 * 16);
        cpa16(st + dst, (const char*)g_xh + src * 2);
        cpa16(st + P_XL + dst, (const char*)g_xl + src * 2);
    }
#pragma unroll
    for (int i = 0; i < 4; i++) {
        int ch = tid + i * 256;
        int r = ch >> 3, c16 = ch & 7;
        size_t src = (size_t)which * (D_ * C_) + (size_t)r * C_ + c0 + c16 * 8;
        uint32_t dst = (uint32_t)(r * 144 + c16 * 16);
        cpa16(st + P_WH + dst, (const char*)g_wh + src * 2);
        cpa16(st + P_WL + dst, (const char*)g_wl + src * 2);
    }
}

__global__ void __launch_bounds__(256) proj_mma_kernel()
{
    extern __shared__ char smem[];
    uint32_t sb = smem_to_u32(smem);
    const int tid = threadIdx.x;
    const int w = tid >> 5, lane = tid & 31;
    const int g = lane >> 2, tq = lane & 3;
    const int b = blockIdx.z, which = blockIdx.y;
    const int n0 = blockIdx.x * 128;

    proj_ld(sb, 0, b, which, 0, n0, tid);
    CP_COMMIT();
    proj_ld(sb, 1, b, which, 64, n0, tid);
    CP_COMMIT();

    float acc[16][4];
#pragma unroll
    for (int j = 0; j < 16; j++)
#pragma unroll
        for (int e = 0; e < 4; e++) acc[j][e] = 0.f;

    const int l7 = lane & 7, lb3 = (lane >> 3) & 1, lb4 = lane >> 4;
    const uint32_t laneAX = (uint32_t)((l7 + lb4 * 8) * 272 + (lb3 * 8) * 2);
    const uint32_t laneBW = (uint32_t)((lb4 * 8 + l7) * 144 + lb3 * 16);
    const uint32_t laneAW = (uint32_t)((l7 + lb3 * 8) * 144 + lb4 * 16);
    const uint32_t laneBX = (uint32_t)((l7 + lb3 * 8) * 272 + (lb4 * 8) * 2);

    int st = 0;
    for (int it = 0; it < 4; it++) {
        if (it + 1 < 4) {
            asm volatile("cp.async.wait_group 1;" ::: "memory");
        } else {
            asm volatile("cp.async.wait_group 0;" ::: "memory");
        }
        __syncthreads();
        if (it + 2 < 4) {
            proj_ld(sb, (st >= 1) ? st - 1 : st + 2, b, which, (it + 2) * 64, n0, tid);
            CP_COMMIT();
        }

        const uint32_t XH = sb + (uint32_t)st * PSTG;
        const uint32_t WH = XH + P_WH;

        if (which < 2) {
#pragma unroll
            for (int kk = 0; kk < 4; kk++) {
                uint32_t axh[4], axl[4];
                uint32_t aaddr = XH + (uint32_t)(kk * 16 * 272) + (uint32_t)(w * 16 * 2) + laneAX;
                LDMX4T(axh, aaddr);
                LDMX4T(axl, aaddr + P_XL);
#pragma unroll
                for (int jp = 0; jp < 8; jp++) {
                    uint32_t baddr = WH + (uint32_t)(jp * 16 * 144 + kk * 32) + laneBW;
                    uint32_t bh[4], bl[4];
                    LDMX4(bh, baddr);
                    LDMX4(bl, baddr + (P_WL - P_WH));
                    MMA16816(acc[2 * jp],     axh, bh[0], bh[1]);
                    MMA16816(acc[2 * jp + 1], axh, bh[2], bh[3]);
                    MMA16816(acc[2 * jp],     axl, bh[0], bh[1]);
                    MMA16816(acc[2 * jp + 1], axl, bh[2], bh[3]);
                    MMA16816(acc[2 * jp],     axh, bl[0], bl[1]);
                    MMA16816(acc[2 * jp + 1], axh, bl[2], bl[3]);
                }
            }
        } else {
#pragma unroll
            for (int kk = 0; kk < 4; kk++) {
                uint32_t awh[4], awl[4];
                uint32_t aaddr = WH + (uint32_t)(w * 16 * 144 + kk * 32) + laneAW;
                LDMX4(awh, aaddr);
                LDMX4(awl, aaddr + (P_WL - P_WH));
#pragma unroll
                for (int jp = 0; jp < 8; jp++) {
                    uint32_t baddr = XH + (uint32_t)(kk * 16 * 272) + (uint32_t)(jp * 16 * 2) + laneBX;
                    uint32_t bxh[4], bxl[4];
                    LDMX4T(bxh, baddr);
                    LDMX4T(bxl, baddr + P_XL);
                    MMA16816(acc[2 * jp],     awh, bxh[0], bxh[1]);
                    MMA16816(acc[2 * jp + 1], awh, bxh[2], bxh[3]);
                    MMA16816(acc[2 * jp],     awl, bxh[0], bxh[1]);
                    MMA16816(acc[2 * jp + 1], awl, bxh[2], bxh[3]);
                    MMA16816(acc[2 * jp],     awh, bxl[0], bxl[1]);
                    MMA16816(acc[2 * jp + 1], awh, bxl[2], bxl[3]);
                }
            }
        }
        st = (st == 2) ? 0 : st + 1;
    }

    if (which < 2) {
        uint16_t* hi = (uint16_t*)((which == 0) ? g_qh : g_kh);
        uint16_t* lo = (uint16_t*)((which == 0) ? g_ql : g_kl);
        size_t row0 = ((size_t)b * NPOS + n0 + w * 16 + g) * D_;
        size_t row1 = row0 + (size_t)8 * D_;
#pragma unroll
        for (int j = 0; j < 16; j++) {
            int col = j * 8 + 2 * tq;
            uint32_t lo0, lo1;
            uint32_t h0 = packsplit(acc[j][0], acc[j][1], lo0);
            uint32_t h1 = packsplit(acc[j][2], acc[j][3], lo1);
            *(uint32_t*)(hi + row0 + col) = h0;
            *(uint32_t*)(lo + row0 + col) = lo0;
            *(uint32_t*)(hi + row1 + col) = h1;
            *(uint32_t*)(lo + row1 + col) = lo1;
        }
    } else {
        uint16_t* hi = (uint16_t*)g_vth;
        uint16_t* lo = (uint16_t*)g_vtl;
        size_t row0 = ((size_t)b * D_ + w * 16 + g) * NPOS + n0;
        size_t row1 = row0 + (size_t)8 * NPOS;
#pragma unroll
        for (int j = 0; j < 16; j++) {
            int col = j * 8 + 2 * tq;
            uint32_t lo0, lo1;
            uint32_t h0 = packsplit(acc[j][0], acc[j][1], lo0);
            uint32_t h1 = packsplit(acc[j][2], acc[j][3], lo1);
            *(uint32_t*)(hi + row0 + col) = h0;
            *(uint32_t*)(lo + row0 + col) = lo0;
            *(uint32_t*)(hi + row1 + col) = h1;
            *(uint32_t*)(lo + row1 + col) = lo1;
        }
    }
}

// =============================================================================
// Kernel 2: flash attention (round-11 math).  Qh in registers, Ql in SMEM,
// 2-stage K/V pipeline, S 3-pass + PV 2-pass self-normalized.
// =============================================================================
#define SZ_Q    34816
#define OFF_KV  SZ_Q
#define SZ_KHL  17408
#define SZ_KST  (2 * SZ_KHL)
#define SZ_VHL  18432
#define SZ_VST  (2 * SZ_VHL)
#define SZ_STAGE (SZ_KST + SZ_VST)
#define FLASH_SMEM (OFF_KV + 2 * SZ_STAGE)   // 178176

__device__ __forceinline__ void ld_stage(uint32_t sb, int st, int b, int kt, int tid)
{
    const char* kh = (const char*)(g_kh + ((size_t)b * NPOS + (size_t)kt * BN) * D_);
    const char* kl = (const char*)(g_kl + ((size_t)b * NPOS + (size_t)kt * BN) * D_);
    uint32_t kb = sb + OFF_KV + st * SZ_STAGE;
#pragma unroll
    for (int i = 0; i < 4; i++) {
        int ch = tid + i * 256;
        int r = ch >> 4, c = ch & 15;
        uint32_t off = (uint32_t)(r * 272 + c * 16);
        size_t go = (size_t)r * 256 + c * 16;
        cpa16(kb + off, kh + go);
        cpa16(kb + SZ_KHL + off, kl + go);
    }
    const char* vh = (const char*)(g_vth + (size_t)b * D_ * NPOS + (size_t)kt * BN);
    const char* vl = (const char*)(g_vtl + (size_t)b * D_ * NPOS + (size_t)kt * BN);
    uint32_t vb = kb + SZ_KST;
#pragma unroll
    for (int i = 0; i < 4; i++) {
        int ch = tid + i * 256;
        int r = ch >> 3, c = ch & 7;
        uint32_t off = (uint32_t)(r * 144 + c * 16);
        size_t go = (size_t)r * (NPOS * 2) + c * 16;
        cpa16(vb + off, vh + go);
        cpa16(vb + SZ_VHL + off, vl + go);
    }
}

// S for one chunk-pair p (kv cols 32p..32p+31): Qh regs, Ql smem.
__device__ __forceinline__ void s_pair(float (&s)[2][2][4], uint32_t Kst, int p,
                                       const uint32_t (&qhr)[8][4],
                                       uint32_t qbase, uint32_t laneK)
{
#pragma unroll
    for (int jc = 0; jc < 2; jc++)
#pragma unroll
        for (int h = 0; h < 2; h++)
#pragma unroll
            for (int e = 0; e < 4; e++) s[jc][h][e] = 0.f;
#pragma unroll
    for (int kk = 0; kk < 8; kk++) {
        uint32_t ql[4];
        LDMX4(ql, qbase + kk * 32);
        uint32_t a0 = Kst + (uint32_t)((2 * p) * (16 * 272) + kk * 32) + laneK;
        uint32_t a1 = a0 + (16 * 272);
        uint32_t bh0[4], bl0[4], bh1[4], bl1[4];
        LDMX4(bh0, a0);
        LDMX4(bl0, a0 + SZ_KHL);
        LDMX4(bh1, a1);
        LDMX4(bl1, a1 + SZ_KHL);
        MMA16816(s[0][0], qhr[kk], bh0[0], bh0[1]);
        MMA16816(s[0][1], qhr[kk], bh0[2], bh0[3]);
        MMA16816(s[1][0], qhr[kk], bh1[0], bh1[1]);
        MMA16816(s[1][1], qhr[kk], bh1[2], bh1[3]);
        MMA16816(s[0][0], ql, bh0[0], bh0[1]);
        MMA16816(s[0][1], ql, bh0[2], bh0[3]);
        MMA16816(s[1][0], ql, bh1[0], bh1[1]);
        MMA16816(s[1][1], ql, bh1[2], bh1[3]);
        MMA16816(s[0][0], qhr[kk], bl0[0], bl0[1]);
        MMA16816(s[0][1], qhr[kk], bl0[2], bl0[3]);
        MMA16816(s[1][0], qhr[kk], bl1[0], bl1[1]);
        MMA16816(s[1][1], qhr[kk], bl1[2], bl1[3]);
    }
}

__device__ __forceinline__ void sm_pv(const float (&sc)[2][4], int jp,
                                      uint32_t Vst, uint32_t laneV,
                                      float (&oacc)[16][4], float& lr0, float& lr1)
{
    uint32_t phj[4];
    {
        float h0, h1;
        float p0 = __expf(sc[0][0] - MFIX), p1 = __expf(sc[0][1] - MFIX);
        float p2 = __expf(sc[0][2] - MFIX), p3 = __expf(sc[0][3] - MFIX);
        phj[0] = packtrunc(p0, p1, h0, h1); lr0 += h0 + h1;
        phj[1] = packtrunc(p2, p3, h0, h1); lr1 += h0 + h1;
        float q0 = __expf(sc[1][0] - MFIX), q1 = __expf(sc[1][1] - MFIX);
        float q2 = __expf(sc[1][2] - MFIX), q3 = __expf(sc[1][3] - MFIX);
        phj[2] = packtrunc(q0, q1, h0, h1); lr0 += h0 + h1;
        phj[3] = packtrunc(q2, q3, h0, h1); lr1 += h0 + h1;
    }
#pragma unroll
    for (int j2 = 0; j2 < 8; j2 += 2) {
        uint32_t aa = Vst + (uint32_t)(j2 * (16 * 144) + jp * 32) + laneV;
        uint32_t ab = aa + (16 * 144);
        uint32_t vha[4], vla[4], vhb[4], vlb[4];
        LDMX4(vha, aa);
        LDMX4(vla, aa + SZ_VHL);
        LDMX4(vhb, ab);
        LDMX4(vlb, ab + SZ_VHL);
        MMA16816(oacc[2 * j2],     phj, vha[0], vha[1]);
        MMA16816(oacc[2 * j2 + 1], phj, vha[2], vha[3]);
        MMA16816(oacc[2 * j2 + 2], phj, vhb[0], vhb[1]);
        MMA16816(oacc[2 * j2 + 3], phj, vhb[2], vhb[3]);
        MMA16816(oacc[2 * j2],     phj, vla[0], vla[1]);
        MMA16816(oacc[2 * j2 + 1], phj, vla[2], vla[3]);
        MMA16816(oacc[2 * j2 + 2], phj, vlb[0], vlb[1]);
        MMA16816(oacc[2 * j2 + 3], phj, vlb[2], vlb[3]);
    }
}

__global__ void __launch_bounds__(256, 1) flash_kernel()
{
    extern __shared__ char smem[];
    uint32_t sb = smem_to_u32(smem);
    const int tid = threadIdx.x;
    const int w = tid >> 5, lane = tid & 31;
    const int g = lane >> 2, tq = lane & 3;
    const int q0 = blockIdx.x * 128;
    const int split = blockIdx.y;
    const int b = blockIdx.z;
    const int ks = (split * 98) / 3;
    const int ke = ((split + 1) * 98) / 3;

    // prologue: Ql -> smem + stage0 (group0); stage1 (group1)
    {
        const char* gql = (const char*)(g_ql + ((size_t)b * NPOS + q0) * D_);
#pragma unroll
        for (int i = 0; i < 8; i++) {
            int ch = tid + i * 256;
            int r = ch >> 4, c = ch & 15;
            cpa16(sb + (uint32_t)(r * 272 + c * 16), gql + (size_t)r * 256 + c * 16);
        }
    }
    ld_stage(sb, 0, b, ks, tid);
    CP_COMMIT();
    ld_stage(sb, 1, b, ks + 1, tid);
    CP_COMMIT();

    // Qh fragments in registers (persist across all tiles)
    uint32_t qhr[8][4];
    {
        const uint16_t* gh = (const uint16_t*)(g_qh + ((size_t)b * NPOS + q0 + w * 16) * D_);
#pragma unroll
        for (int kk = 0; kk < 8; kk++) {
            size_t o0 = (size_t)g * 128 + kk * 16 + 2 * tq;
            size_t o1 = (size_t)(g + 8) * 128 + kk * 16 + 2 * tq;
            qhr[kk][0] = *(const uint32_t*)(gh + o0);
            qhr[kk][1] = *(const uint32_t*)(gh + o1);
            qhr[kk][2] = *(const uint32_t*)(gh + o0 + 8);
            qhr[kk][3] = *(const uint32_t*)(gh + o1 + 8);
        }
    }

    float oacc[16][4];
#pragma unroll
    for (int j = 0; j < 16; j++)
#pragma unroll
        for (int e = 0; e < 4; e++) oacc[j][e] = 0.f;
    float lr0 = 0.f, lr1 = 0.f;

    const int r8 = lane & 7, half = (lane >> 3) & 1, jjo = lane >> 4;
    const uint32_t laneK = (uint32_t)((jjo * 8 + r8) * 272 + half * 16);
    const uint32_t laneV = (uint32_t)((jjo * 8 + r8) * 144 + half * 16);
    const uint32_t qbase = sb + (uint32_t)((w * 16 + half * 8 + r8) * 272 + jjo * 16);

    int st = 0;
    for (int t = ks; t < ke; t++) {
        if (t + 1 < ke) {
            asm volatile("cp.async.wait_group 1;" ::: "memory");
        } else {
            asm volatile("cp.async.wait_group 0;" ::: "memory");
        }
        __syncthreads();

        const uint32_t Kst = sb + OFF_KV + st * SZ_STAGE;
        const uint32_t Vst = Kst + SZ_KST;

        float sA[2][2][4], sB[2][2][4];
        s_pair(sA, Kst, 0, qhr, qbase, laneK);
        s_pair(sB, Kst, 1, qhr, qbase, laneK);
        sm_pv(sA[0], 0, Vst, laneV, oacc, lr0, lr1);
        sm_pv(sA[1], 1, Vst, laneV, oacc, lr0, lr1);
        sm_pv(sB[0], 2, Vst, laneV, oacc, lr0, lr1);
        sm_pv(sB[1], 3, Vst, laneV, oacc, lr0, lr1);

        __syncthreads();
        if (t + 2 < ke) {
            ld_stage(sb, st, b, t + 2, tid);
            CP_COMMIT();
        }
        st ^= 1;
    }

    lr0 += __shfl_xor_sync(0xffffffffu, lr0, 1);
    lr0 += __shfl_xor_sync(0xffffffffu, lr0, 2);
    lr1 += __shfl_xor_sync(0xffffffffu, lr1, 1);
    lr1 += __shfl_xor_sync(0xffffffffu, lr1, 2);
    if (tq == 0) {
        size_t base = (size_t)b * NPOS + q0 + w * 16;
        g_lp[split][base + g] = lr0;
        g_lp[split][base + g + 8] = lr1;
    }

    float* yd = g_yp[split] + ((size_t)b * NPOS + q0 + w * 16) * D_;
#pragma unroll
    for (int j = 0; j < 16; j++) {
        *(float2*)(yd + (size_t)g * D_ + j * 8 + 2 * tq) = make_float2(oacc[j][0], oacc[j][1]);
        *(float2*)(yd + (size_t)(g + 8) * D_ + j * 8 + 2 * tq) = make_float2(oacc[j][2], oacc[j][3]);
    }
}

// =============================================================================
// Kernel 3 (mma): out[b][c][n] = x + Wz @ (Σ_s y_s / L).  n-tile 128.
// grid (49, 2, 4), 256 threads.  tile 128c x 128n x 128d.
// =============================================================================
#define EPI_WZH  0
#define EPI_WZL  34816
#define EPI_YH   69632
#define EPI_YL   104448
#define EPI_LINV 139264
#define EPI_SMEM (EPI_LINV + 512)

__global__ void __launch_bounds__(256) epi_kernel(
    const float* __restrict__ Wz, const float* __restrict__ x, float* __restrict__ out)
{
    extern __shared__ char smem[];
    uint32_t sb = smem_to_u32(smem);
    const int tid = threadIdx.x;
    const int w = tid >> 5, lane = tid & 31;
    const int g = lane >> 2, tq = lane & 3;
    const int b = blockIdx.z;
    const int c0 = blockIdx.y * 128;
    const int n0 = blockIdx.x * 128;

    float* linv = (float*)(smem + EPI_LINV);
    if (tid < 128) {
        size_t li = (size_t)b * NPOS + n0 + tid;
        linv[tid] = 1.f / (g_lp[0][li] + g_lp[1][li] + g_lp[2][li]);
    }
    __syncthreads();

    for (int v = tid; v < 128 * 32; v += 256) {
        int r = v >> 5, c = v & 31;
        float4 wv = *(const float4*)(Wz + (size_t)(c0 + r) * D_ + 4 * c);
        uint32_t l0, l1;
        uint32_t h0 = packsplit(wv.x, wv.y, l0);
        uint32_t h1 = packsplit(wv.z, wv.w, l1);
        *(uint2*)(smem + EPI_WZH + r * 272 + c * 8) = make_uint2(h0, h1);
        *(uint2*)(smem + EPI_WZL + r * 272 + c * 8) = make_uint2(l0, l1);
    }
    {
        const float* y0 = g_yp[0] + ((size_t)b * NPOS + n0) * D_;
        const float* y1 = g_yp[1] + ((size_t)b * NPOS + n0) * D_;
        const float* y2 = g_yp[2] + ((size_t)b * NPOS + n0) * D_;
        for (int v = tid; v < 128 * 32; v += 256) {
            int r = v >> 5, c = v & 31;
            size_t o = (size_t)r * D_ + 4 * c;
            float4 a = *(const float4*)(y0 + o);
            float4 bb = *(const float4*)(y1 + o);
            float4 cc = *(const float4*)(y2 + o);
            float s = linv[r];
            float vx = (a.x + bb.x + cc.x) * s;
            float vy = (a.y + bb.y + cc.y) * s;
            float vz = (a.z + bb.z + cc.z) * s;
            float vw = (a.w + bb.w + cc.w) * s;
            uint32_t l0, l1;
            uint32_t h0 = packsplit(vx, vy, l0);
            uint32_t h1 = packsplit(vz, vw, l1);
            *(uint2*)(smem + EPI_YH + r * 272 + c * 8) = make_uint2(h0, h1);
            *(uint2*)(smem + EPI_YL + r * 272 + c * 8) = make_uint2(l0, l1);
        }
    }
    __syncthreads();

    float acc[16][4];
#pragma unroll
    for (int j = 0; j < 16; j++)
#pragma unroll
        for (int e = 0; e < 4; e++) acc[j][e] = 0.f;

    const int r8 = lane & 7;
    const uint32_t laneA = (uint32_t)((((lane >> 3) & 1) * 8 + r8) * 272 + (lane >> 4) * 16);
    const uint32_t laneB = (uint32_t)(((lane >> 4) * 8 + r8) * 272 + ((lane >> 3) & 1) * 16);
    const uint32_t wA = sb + EPI_WZH + (uint32_t)(w * 16 * 272);

#pragma unroll
    for (int kk = 0; kk < 8; kk++) {
        uint32_t ah[4], al[4];
        LDMX4(ah, wA + kk * 32 + laneA);
        LDMX4(al, wA + (EPI_WZL - EPI_WZH) + kk * 32 + laneA);
#pragma unroll
        for (int jp = 0; jp < 8; jp++) {
            uint32_t ba = sb + EPI_YH + (uint32_t)(jp * (16 * 272) + kk * 32) + laneB;
            uint32_t bh[4], bl[4];
            LDMX4(bh, ba);
            LDMX4(bl, ba + (EPI_YL - EPI_YH));
            MMA16816(acc[2 * jp],     ah, bh[0], bh[1]);
            MMA16816(acc[2 * jp + 1], ah, bh[2], bh[3]);
            MMA16816(acc[2 * jp],     al, bh[0], bh[1]);
            MMA16816(acc[2 * jp + 1], al, bh[2], bh[3]);
            MMA16816(acc[2 * jp],     ah, bl[0], bl[1]);
            MMA16816(acc[2 * jp + 1], ah, bl[2], bl[3]);
        }
    }

    const size_t row0 = (size_t)(b * C_ + c0 + w * 16 + g) * NPOS + n0;
    const size_t row1 = row0 + (size_t)8 * NPOS;
#pragma unroll
    for (int j = 0; j < 16; j++) {
        int col = j * 8 + 2 * tq;
        float2 x0 = *(const float2*)(x + row0 + col);
        float2 x1 = *(const float2*)(x + row1 + col);
        *(float2*)(out + row0 + col) = make_float2(acc[j][0] + x0.x, acc[j][1] + x0.y);
        *(float2*)(out + row1 + col) = make_float2(acc[j][2] + x1.x, acc[j][3] + x1.y);
    }
}

// =============================================================================
extern "C" void kernel_launch(void* const* d_in, const int* in_sizes, int n_in,
                              void* d_out, int out_size)
{
    const float* x      = (const float*)d_in[0];
    const float* Wg     = (const float*)d_in[1];
    const float* Wtheta = (const float*)d_in[2];
    const float* Wphi   = (const float*)d_in[3];
    const float* Wz     = (const float*)d_in[4];
    float* out = (float*)d_out;

    cudaFuncSetAttribute(proj_mma_kernel, cudaFuncAttributeMaxDynamicSharedMemorySize, PROJ_SMEM);
    cudaFuncSetAttribute(flash_kernel, cudaFuncAttributeMaxDynamicSharedMemorySize, FLASH_SMEM);
    cudaFuncSetAttribute(epi_kernel, cudaFuncAttributeMaxDynamicSharedMemorySize, EPI_SMEM);

    split_x_kernel<<<6272, 256>>>(x);
    split_w_kernel<<<dim3(32, 3), 256>>>(Wtheta, Wphi, Wg);
    proj_mma_kernel<<<dim3(NPOS / 128, 3, B_), 256, PROJ_SMEM>>>();
    flash_kernel<<<dim3(NPOS / 128, NSPLIT, B_), 256, FLASH_SMEM>>>();
    epi_kernel<<<dim3(NPOS / 128, C_ / 128, B_), 256, EPI_SMEM>>>(Wz, x, out);
}

// round 14
// speedup vs baseline: 1.0291x; 1.0291x over previous
#include <cuda_runtime.h>
#include <cuda_bf16.h>
#include <cstdint>
#include <math.h>

#define B_    4
#define C_    256
#define D_    128
#define NPOS  6272
#define BN    64
#define NSPLIT 3
#define MFIX  80.0f

// ---------------- scratch (static __device__, no allocation) ----------------
__device__ __nv_bfloat16 g_xh[(size_t)B_ * C_ * NPOS];
__device__ __nv_bfloat16 g_xl[(size_t)B_ * C_ * NPOS];
__device__ __nv_bfloat16 g_wh[3 * D_ * C_];
__device__ __nv_bfloat16 g_wl[3 * D_ * C_];
__device__ __nv_bfloat16 g_qh[(size_t)B_ * NPOS * D_];
__device__ __nv_bfloat16 g_ql[(size_t)B_ * NPOS * D_];
__device__ __nv_bfloat16 g_kh[(size_t)B_ * NPOS * D_];
__device__ __nv_bfloat16 g_kl[(size_t)B_ * NPOS * D_];
__device__ __nv_bfloat16 g_vth[(size_t)B_ * D_ * NPOS];  // V^T [b][d][n]
__device__ __nv_bfloat16 g_vtl[(size_t)B_ * D_ * NPOS];
__device__ float g_yp[NSPLIT][(size_t)B_ * NPOS * D_];   // unnormalized partial O
__device__ float g_lp[NSPLIT][(size_t)B_ * NPOS];        // partial l

// ======================= helpers ==================
__device__ __forceinline__ uint32_t smem_to_u32(const void* p) {
    uint32_t a;
    asm("{ .reg .u64 t; cvta.to.shared.u64 t, %1; cvt.u32.u64 %0, t; }" : "=r"(a) : "l"(p));
    return a;
}
__device__ __forceinline__ void cpa16(uint32_t s, const void* g) {
    asm volatile("cp.async.cg.shared.global [%0], [%1], 16;" :: "r"(s), "l"(g));
}
#define CP_COMMIT() asm volatile("cp.async.commit_group;" ::: "memory")

// D = A(16x16 bf16, row) * B(16x8 bf16, col) + D (f32)
#define MMA16816(c, a, b0_, b1_) \
    asm volatile("mma.sync.aligned.m16n8k16.row.col.f32.bf16.bf16.f32 " \
        "{%0,%1,%2,%3}, {%4,%5,%6,%7}, {%8,%9}, {%0,%1,%2,%3};" \
        : "+f"((c)[0]), "+f"((c)[1]), "+f"((c)[2]), "+f"((c)[3]) \
        : "r"((a)[0]), "r"((a)[1]), "r"((a)[2]), "r"((a)[3]), "r"(b0_), "r"(b1_))

#define LDMX4(rr, addr) \
    asm volatile("ldmatrix.sync.aligned.m8n8.x4.shared.b16 {%0,%1,%2,%3}, [%4];" \
        : "=r"((rr)[0]), "=r"((rr)[1]), "=r"((rr)[2]), "=r"((rr)[3]) : "r"(addr))
#define LDMX4T(rr, addr) \
    asm volatile("ldmatrix.sync.aligned.m8n8.x4.trans.shared.b16 {%0,%1,%2,%3}, [%4];" \
        : "=r"((rr)[0]), "=r"((rr)[1]), "=r"((rr)[2]), "=r"((rr)[3]) : "r"(addr))

// split f32 pair -> hi(trunc) packed bf16x2 (a in low half) + lo(rn) packed
__device__ __forceinline__ uint32_t packsplit(float a, float b, uint32_t& lo) {
    uint32_t ua = __float_as_uint(a), ub = __float_as_uint(b);
    float r0 = a - __uint_as_float(ua & 0xFFFF0000u);
    float r1 = b - __uint_as_float(ub & 0xFFFF0000u);
    asm("cvt.rn.bf16x2.f32 %0, %1, %2;" : "=r"(lo) : "f"(r1), "f"(r0));
    return (ua >> 16) | (ub & 0xFFFF0000u);
}

// trunc-pack only, and return the truncated hi values as floats (for l = Σph)
__device__ __forceinline__ uint32_t packtrunc(float a, float b, float& ha, float& hb) {
    uint32_t ua = __float_as_uint(a), ub = __float_as_uint(b);
    ha = __uint_as_float(ua & 0xFFFF0000u);
    hb = __uint_as_float(ub & 0xFFFF0000u);
    return (ua >> 16) | (ub & 0xFFFF0000u);
}

// =============================================================================
// Kernel 0a: split x -> bf16 hi/lo.
// =============================================================================
__global__ void __launch_bounds__(256) split_x_kernel(const float* __restrict__ x)
{
    size_t i = ((size_t)blockIdx.x * 256 + threadIdx.x) * 4;
    float4 v = *(const float4*)(x + i);
    uint32_t l0, l1;
    uint32_t h0 = packsplit(v.x, v.y, l0);
    uint32_t h1 = packsplit(v.z, v.w, l1);
    *(uint2*)((uint16_t*)g_xh + i) = make_uint2(h0, h1);
    *(uint2*)((uint16_t*)g_xl + i) = make_uint2(l0, l1);
}

// Kernel 0b: split W{theta,phi,g} -> bf16 hi/lo.
__global__ void __launch_bounds__(256) split_w_kernel(
    const float* __restrict__ Wt, const float* __restrict__ Wp,
    const float* __restrict__ Wg_)
{
    int which = blockIdx.y;
    const float* W = (which == 0) ? Wt : (which == 1) ? Wp : Wg_;
    size_t i = ((size_t)blockIdx.x * 256 + threadIdx.x) * 4;
    float4 v = *(const float4*)(W + i);
    uint32_t l0, l1;
    uint32_t h0 = packsplit(v.x, v.y, l0);
    uint32_t h1 = packsplit(v.z, v.w, l1);
    size_t o = (size_t)which * (D_ * C_) + i;
    *(uint2*)((uint16_t*)g_wh + o) = make_uint2(h0, h1);
    *(uint2*)((uint16_t*)g_wl + o) = make_uint2(l0, l1);
}

// =============================================================================
// Kernel 1: proj via mma.sync (3-pass bf16 emulation).  k-chunk 32, 8 iters.
// grid (49, 3, B), 256 thr.  which: 0=theta->Q, 1=phi->K, 2=g->V^T.
// =============================================================================
#define PSTG 37888
#define PROJ_SMEM (3 * PSTG)

__device__ __forceinline__ void proj_ld(uint32_t sb, int s, int b, int which,
                                        int c0, int n0, int tid)
{
    uint32_t st = sb + (uint32_t)s * PSTG;
#pragma unroll
    for (int i = 0; i < 2; i++) {
        int ch = tid + i * 256;
        int r = ch >> 4, c16 = ch & 15;
        size_t src = ((size_t)(b * C_ + c0 + r)) * NPOS + n0 + c16 * 8;
        uint32_t dst = (uint32_t)(r * 272 + c16 * 16);
        cpa16(st + dst, (const char*)g_xh + src * 2);
        cpa16(st + 8704 + dst, (const char*)g_xl + src * 2);
    }
#pragma unroll
    for (int i = 0; i < 2; i++) {
        int ch = tid + i * 256;
        int r = ch >> 2, c16 = ch & 3;
        size_t src = (size_t)which * (D_ * C_) + (size_t)r * C_ + c0 + c16 * 8;
        uint32_t dst = (uint32_t)(r * 80 + c16 * 16);
        cpa16(st + 17408 + dst, (const char*)g_wh + src * 2);
        cpa16(st + 27648 + dst, (const char*)g_wl + src * 2);
    }
}

__global__ void __launch_bounds__(256) proj_mma_kernel()
{
    extern __shared__ char smem[];
    uint32_t sb = smem_to_u32(smem);
    const int tid = threadIdx.x;
    const int w = tid >> 5, lane = tid & 31;
    const int g = lane >> 2, tq = lane & 3;
    const int b = blockIdx.z, which = blockIdx.y;
    const int n0 = blockIdx.x * 128;

    proj_ld(sb, 0, b, which, 0, n0, tid);
    CP_COMMIT();
    proj_ld(sb, 1, b, which, 32, n0, tid);
    CP_COMMIT();

    float acc[16][4];
#pragma unroll
    for (int j = 0; j < 16; j++)
#pragma unroll
        for (int e = 0; e < 4; e++) acc[j][e] = 0.f;

    const int l7 = lane & 7, lb3 = (lane >> 3) & 1, lb4 = lane >> 4;
    const uint32_t laneAX = (uint32_t)((l7 + lb4 * 8) * 272 + (lb3 * 8) * 2);
    const uint32_t laneBW = (uint32_t)((lb4 * 8 + l7) * 80 + lb3 * 16);
    const uint32_t laneAW = (uint32_t)((l7 + lb3 * 8) * 80 + lb4 * 16);
    const uint32_t laneBX = (uint32_t)((l7 + lb3 * 8) * 272 + (lb4 * 8) * 2);

    int st = 0;
    for (int it = 0; it < 8; it++) {
        if (it + 1 < 8) {
            asm volatile("cp.async.wait_group 1;" ::: "memory");
        } else {
            asm volatile("cp.async.wait_group 0;" ::: "memory");
        }
        __syncthreads();
        if (it + 2 < 8) {
            proj_ld(sb, (st >= 1) ? st - 1 : st + 2, b, which, (it + 2) * 32, n0, tid);
            CP_COMMIT();
        }

        const uint32_t XH = sb + (uint32_t)st * PSTG;
        const uint32_t WH = XH + 17408;

        if (which < 2) {
#pragma unroll
            for (int kk = 0; kk < 2; kk++) {
                uint32_t axh[4], axl[4];
                uint32_t aaddr = XH + (uint32_t)(kk * 16 * 272) + (uint32_t)(w * 16 * 2) + laneAX;
                LDMX4T(axh, aaddr);
                LDMX4T(axl, aaddr + 8704);
#pragma unroll
                for (int jp = 0; jp < 8; jp++) {
                    uint32_t baddr = WH + (uint32_t)(jp * 16 * 80 + kk * 32) + laneBW;
                    uint32_t bh[4], bl[4];
                    LDMX4(bh, baddr);
                    LDMX4(bl, baddr + 10240);
                    MMA16816(acc[2 * jp],     axh, bh[0], bh[1]);
                    MMA16816(acc[2 * jp + 1], axh, bh[2], bh[3]);
                    MMA16816(acc[2 * jp],     axl, bh[0], bh[1]);
                    MMA16816(acc[2 * jp + 1], axl, bh[2], bh[3]);
                    MMA16816(acc[2 * jp],     axh, bl[0], bl[1]);
                    MMA16816(acc[2 * jp + 1], axh, bl[2], bl[3]);
                }
            }
        } else {
#pragma unroll
            for (int kk = 0; kk < 2; kk++) {
                uint32_t awh[4], awl[4];
                uint32_t aaddr = WH + (uint32_t)(w * 16 * 80 + kk * 32) + laneAW;
                LDMX4(awh, aaddr);
                LDMX4(awl, aaddr + 10240);
#pragma unroll
                for (int jp = 0; jp < 8; jp++) {
                    uint32_t baddr = XH + (uint32_t)(kk * 16 * 272) + (uint32_t)(jp * 16 * 2) + laneBX;
                    uint32_t bxh[4], bxl[4];
                    LDMX4T(bxh, baddr);
                    LDMX4T(bxl, baddr + 8704);
                    MMA16816(acc[2 * jp],     awh, bxh[0], bxh[1]);
                    MMA16816(acc[2 * jp + 1], awh, bxh[2], bxh[3]);
                    MMA16816(acc[2 * jp],     awl, bxh[0], bxh[1]);
                    MMA16816(acc[2 * jp + 1], awl, bxh[2], bxh[3]);
                    MMA16816(acc[2 * jp],     awh, bxl[0], bxl[1]);
                    MMA16816(acc[2 * jp + 1], awh, bxl[2], bxl[3]);
                }
            }
        }
        st = (st == 2) ? 0 : st + 1;
    }

    if (which < 2) {
        uint16_t* hi = (uint16_t*)((which == 0) ? g_qh : g_kh);
        uint16_t* lo = (uint16_t*)((which == 0) ? g_ql : g_kl);
        size_t row0 = ((size_t)b * NPOS + n0 + w * 16 + g) * D_;
        size_t row1 = row0 + (size_t)8 * D_;
#pragma unroll
        for (int j = 0; j < 16; j++) {
            int col = j * 8 + 2 * tq;
            uint32_t lo0, lo1;
            uint32_t h0 = packsplit(acc[j][0], acc[j][1], lo0);
            uint32_t h1 = packsplit(acc[j][2], acc[j][3], lo1);
            *(uint32_t*)(hi + row0 + col) = h0;
            *(uint32_t*)(lo + row0 + col) = lo0;
            *(uint32_t*)(hi + row1 + col) = h1;
            *(uint32_t*)(lo + row1 + col) = lo1;
        }
    } else {
        uint16_t* hi = (uint16_t*)g_vth;
        uint16_t* lo = (uint16_t*)g_vtl;
        size_t row0 = ((size_t)b * D_ + w * 16 + g) * NPOS + n0;
        size_t row1 = row0 + (size_t)8 * NPOS;
#pragma unroll
        for (int j = 0; j < 16; j++) {
            int col = j * 8 + 2 * tq;
            uint32_t lo0, lo1;
            uint32_t h0 = packsplit(acc[j][0], acc[j][1], lo0);
            uint32_t h1 = packsplit(acc[j][2], acc[j][3], lo1);
            *(uint32_t*)(hi + row0 + col) = h0;
            *(uint32_t*)(lo + row0 + col) = lo0;
            *(uint32_t*)(hi + row1 + col) = h1;
            *(uint32_t*)(lo + row1 + col) = lo1;
        }
    }
}

// =============================================================================
// Kernel 2: flash attention (round-11: Q hi/lo in SMEM, 2-stage K/V,
// S 3-pass + PV 2-pass self-normalized with l = Σ truncated-P).
// =============================================================================
#define SZ_Q    34816
#define OFF_KV  (2 * SZ_Q)
#define SZ_KHL  17408
#define SZ_KST  (2 * SZ_KHL)
#define SZ_VHL  18432
#define SZ_VST  (2 * SZ_VHL)
#define SZ_STAGE (SZ_KST + SZ_VST)
#define FLASH_SMEM (OFF_KV + 2 * SZ_STAGE)   // 212992

__device__ __forceinline__ void ld_stage(uint32_t sb, int st, int b, int kt, int tid)
{
    const char* kh = (const char*)(g_kh + ((size_t)b * NPOS + (size_t)kt * BN) * D_);
    const char* kl = (const char*)(g_kl + ((size_t)b * NPOS + (size_t)kt * BN) * D_);
    uint32_t kb = sb + OFF_KV + st * SZ_STAGE;
#pragma unroll
    for (int i = 0; i < 4; i++) {
        int ch = tid + i * 256;
        int r = ch >> 4, c = ch & 15;
        uint32_t off = (uint32_t)(r * 272 + c * 16);
        size_t go = (size_t)r * 256 + c * 16;
        cpa16(kb + off, kh + go);
        cpa16(kb + SZ_KHL + off, kl + go);
    }
    const char* vh = (const char*)(g_vth + (size_t)b * D_ * NPOS + (size_t)kt * BN);
    const char* vl = (const char*)(g_vtl + (size_t)b * D_ * NPOS + (size_t)kt * BN);
    uint32_t vb = kb + SZ_KST;
#pragma unroll
    for (int i = 0; i < 4; i++) {
        int ch = tid + i * 256;
        int r = ch >> 3, c = ch & 7;
        uint32_t off = (uint32_t)(r * 144 + c * 16);
        size_t go = (size_t)r * (NPOS * 2) + c * 16;
        cpa16(vb + off, vh + go);
        cpa16(vb + SZ_VHL + off, vl + go);
    }
}

// S for one chunk-pair p (kv cols 32p .. 32p+31): Q frags from smem.
__device__ __forceinline__ void s_pair(float (&s)[2][2][4], uint32_t Kst, int p,
                                       uint32_t qbase, uint32_t laneK)
{
#pragma unroll
    for (int jc = 0; jc < 2; jc++)
#pragma unroll
        for (int h = 0; h < 2; h++)
#pragma unroll
            for (int e = 0; e < 4; e++) s[jc][h][e] = 0.f;
#pragma unroll
    for (int kk = 0; kk < 8; kk++) {
        uint32_t qh[4], ql[4];
        LDMX4(qh, qbase + kk * 32);
        LDMX4(ql, qbase + kk * 32 + SZ_Q);
#pragma unroll
        for (int jc = 0; jc < 2; jc++) {
            int jp = 2 * p + jc;
            uint32_t addr = Kst + (uint32_t)(jp * (16 * 272) + kk * 32) + laneK;
            uint32_t bh[4], bl[4];
            LDMX4(bh, addr);
            LDMX4(bl, addr + SZ_KHL);
            MMA16816(s[jc][0], qh, bh[0], bh[1]);
            MMA16816(s[jc][1], qh, bh[2], bh[3]);
            MMA16816(s[jc][0], ql, bh[0], bh[1]);
            MMA16816(s[jc][1], ql, bh[2], bh[3]);
            MMA16816(s[jc][0], qh, bl[0], bl[1]);
            MMA16816(s[jc][1], qh, bl[2], bl[3]);
        }
    }
}

// softmax of one 16-col chunk (P truncated to bf16; l accumulates the SAME
// truncated values) + its 2-pass PV MMAs (Ph*Vh + Ph*Vl).
__device__ __forceinline__ void sm_pv(const float (&sc)[2][4], int jp,
                                      uint32_t Vst, uint32_t laneV,
                                      float (&oacc)[16][4], float& lr0, float& lr1)
{
    uint32_t phj[4];
    {
        float h0, h1;
        float p0 = __expf(sc[0][0] - MFIX), p1 = __expf(sc[0][1] - MFIX);
        float p2 = __expf(sc[0][2] - MFIX), p3 = __expf(sc[0][3] - MFIX);
        phj[0] = packtrunc(p0, p1, h0, h1); lr0 += h0 + h1;
        phj[1] = packtrunc(p2, p3, h0, h1); lr1 += h0 + h1;
        float q0 = __expf(sc[1][0] - MFIX), q1 = __expf(sc[1][1] - MFIX);
        float q2 = __expf(sc[1][2] - MFIX), q3 = __expf(sc[1][3] - MFIX);
        phj[2] = packtrunc(q0, q1, h0, h1); lr0 += h0 + h1;
        phj[3] = packtrunc(q2, q3, h0, h1); lr1 += h0 + h1;
    }
#pragma unroll
    for (int j2 = 0; j2 < 8; j2++) {
        uint32_t addr = Vst + (uint32_t)(j2 * (16 * 144) + jp * 32) + laneV;
        uint32_t vh_[4], vl_[4];
        LDMX4(vh_, addr);
        LDMX4(vl_, addr + SZ_VHL);
        MMA16816(oacc[2 * j2],     phj, vh_[0], vh_[1]);
        MMA16816(oacc[2 * j2 + 1], phj, vh_[2], vh_[3]);
        MMA16816(oacc[2 * j2],     phj, vl_[0], vl_[1]);
        MMA16816(oacc[2 * j2 + 1], phj, vl_[2], vl_[3]);
    }
}

__global__ void __launch_bounds__(256, 1) flash_kernel()
{
    extern __shared__ char smem[];
    uint32_t sb = smem_to_u32(smem);
    const int tid = threadIdx.x;
    const int w = tid >> 5, lane = tid & 31;
    const int g = lane >> 2, tq = lane & 3;
    const int q0 = blockIdx.x * 128;
    const int split = blockIdx.y;
    const int b = blockIdx.z;
    const int ks = (split * 98) / 3;
    const int ke = ((split + 1) * 98) / 3;

    // prologue: Q (hi/lo) + stage0 in group0; stage1 in group1
    {
        const char* gqh = (const char*)(g_qh + ((size_t)b * NPOS + q0) * D_);
        const char* gql = (const char*)(g_ql + ((size_t)b * NPOS + q0) * D_);
#pragma unroll
        for (int i = 0; i < 8; i++) {
            int ch = tid + i * 256;
            int r = ch >> 4, c = ch & 15;
            uint32_t dst = (uint32_t)(r * 272 + c * 16);
            size_t src = (size_t)r * 256 + c * 16;
            cpa16(sb + dst, gqh + src);
            cpa16(sb + SZ_Q + dst, gql + src);
        }
    }
    ld_stage(sb, 0, b, ks, tid);
    CP_COMMIT();
    ld_stage(sb, 1, b, ks + 1, tid);
    CP_COMMIT();

    float oacc[16][4];
#pragma unroll
    for (int j = 0; j < 16; j++)
#pragma unroll
        for (int e = 0; e < 4; e++) oacc[j][e] = 0.f;
    float lr0 = 0.f, lr1 = 0.f;

    const int r8 = lane & 7, half = (lane >> 3) & 1, jjo = lane >> 4;
    const uint32_t laneK = (uint32_t)((jjo * 8 + r8) * 272 + half * 16);
    const uint32_t laneV = (uint32_t)((jjo * 8 + r8) * 144 + half * 16);
    const uint32_t qbase = sb + (uint32_t)((w * 16 + half * 8 + r8) * 272 + jjo * 16);

    int st = 0;
    for (int t = ks; t < ke; t++) {
        if (t + 1 < ke) {
            asm volatile("cp.async.wait_group 1;" ::: "memory");
        } else {
            asm volatile("cp.async.wait_group 0;" ::: "memory");
        }
        __syncthreads();

        const uint32_t Kst = sb + OFF_KV + st * SZ_STAGE;
        const uint32_t Vst = Kst + SZ_KST;

        float sA[2][2][4], sB[2][2][4];
        s_pair(sA, Kst, 0, qbase, laneK);
        s_pair(sB, Kst, 1, qbase, laneK);
        sm_pv(sA[0], 0, Vst, laneV, oacc, lr0, lr1);
        sm_pv(sA[1], 1, Vst, laneV, oacc, lr0, lr1);
        sm_pv(sB[0], 2, Vst, laneV, oacc, lr0, lr1);
        sm_pv(sB[1], 3, Vst, laneV, oacc, lr0, lr1);

        __syncthreads();
        if (t + 2 < ke) {
            ld_stage(sb, st, b, t + 2, tid);
            CP_COMMIT();
        }
        st ^= 1;
    }

    lr0 += __shfl_xor_sync(0xffffffffu, lr0, 1);
    lr0 += __shfl_xor_sync(0xffffffffu, lr0, 2);
    lr1 += __shfl_xor_sync(0xffffffffu, lr1, 1);
    lr1 += __shfl_xor_sync(0xffffffffu, lr1, 2);
    if (tq == 0) {
        size_t base = (size_t)b * NPOS + q0 + w * 16;
        g_lp[split][base + g] = lr0;
        g_lp[split][base + g + 8] = lr1;
    }

    float* yd = g_yp[split] + ((size_t)b * NPOS + q0 + w * 16) * D_;
#pragma unroll
    for (int j = 0; j < 16; j++) {
        *(float2*)(yd + (size_t)g * D_ + j * 8 + 2 * tq) = make_float2(oacc[j][0], oacc[j][1]);
        *(float2*)(yd + (size_t)(g + 8) * D_ + j * 8 + 2 * tq) = make_float2(oacc[j][2], oacc[j][3]);
    }
}

// =============================================================================
// Kernel 3 (mma): out[b][c][n] = x + Wz @ (Σ_s y_s / L).  n-tile 64.
// =============================================================================
#define EPI_WZH  0
#define EPI_WZL  34816
#define EPI_YH   69632
#define EPI_YL   87040
#define EPI_LINV 104448
#define EPI_SMEM (EPI_LINV + 256)

__global__ void __launch_bounds__(256) epi_kernel(
    const float* __restrict__ Wz, const float* __restrict__ x, float* __restrict__ out)
{
    extern __shared__ char smem[];
    uint32_t sb = smem_to_u32(smem);
    const int tid = threadIdx.x;
    const int w = tid >> 5, lane = tid & 31;
    const int g = lane >> 2, tq = lane & 3;
    const int b = blockIdx.z;
    const int c0 = blockIdx.y * 128;
    const int n0 = blockIdx.x * 64;

    float* linv = (float*)(smem + EPI_LINV);
    if (tid < 64) {
        size_t li = (size_t)b * NPOS + n0 + tid;
        linv[tid] = 1.f / (g_lp[0][li] + g_lp[1][li] + g_lp[2][li]);
    }
    __syncthreads();

    for (int v = tid; v < 128 * 32; v += 256) {
        int r = v >> 5, c = v & 31;
        float4 wv = *(const float4*)(Wz + (size_t)(c0 + r) * D_ + 4 * c);
        uint32_t l0, l1;
        uint32_t h0 = packsplit(wv.x, wv.y, l0);
        uint32_t h1 = packsplit(wv.z, wv.w, l1);
        *(uint2*)(smem + EPI_WZH + r * 272 + c * 8) = make_uint2(h0, h1);
        *(uint2*)(smem + EPI_WZL + r * 272 + c * 8) = make_uint2(l0, l1);
    }
    {
        const float* y0 = g_yp[0] + ((size_t)b * NPOS + n0) * D_;
        const float* y1 = g_yp[1] + ((size_t)b * NPOS + n0) * D_;
        const float* y2 = g_yp[2] + ((size_t)b * NPOS + n0) * D_;
        for (int v = tid; v < 64 * 32; v += 256) {
            int r = v >> 5, c = v & 31;
            size_t o = (size_t)r * D_ + 4 * c;
            float4 a = *(const float4*)(y0 + o);
            float4 bb = *(const float4*)(y1 + o);
            float4 cc = *(const float4*)(y2 + o);
            float s = linv[r];
            float vx = (a.x + bb.x + cc.x) * s;
            float vy = (a.y + bb.y + cc.y) * s;
            float vz = (a.z + bb.z + cc.z) * s;
            float vw = (a.w + bb.w + cc.w) * s;
            uint32_t l0, l1;
            uint32_t h0 = packsplit(vx, vy, l0);
            uint32_t h1 = packsplit(vz, vw, l1);
            *(uint2*)(smem + EPI_YH + r * 272 + c * 8) = make_uint2(h0, h1);
            *(uint2*)(smem + EPI_YL + r * 272 + c * 8) = make_uint2(l0, l1);
        }
    }
    __syncthreads();

    float acc[8][4];
#pragma unroll
    for (int j = 0; j < 8; j++)
#pragma unroll
        for (int e = 0; e < 4; e++) acc[j][e] = 0.f;

    const int r8 = lane & 7;
    const uint32_t laneA = (uint32_t)((((lane >> 3) & 1) * 8 + r8) * 272 + (lane >> 4) * 16);
    const uint32_t laneB = (uint32_t)(((lane >> 4) * 8 + r8) * 272 + ((lane >> 3) & 1) * 16);
    const uint32_t wA = sb + EPI_WZH + (uint32_t)(w * 16 * 272);

#pragma unroll
    for (int kk = 0; kk < 8; kk++) {
        uint32_t ah[4], al[4];
        LDMX4(ah, wA + kk * 32 + laneA);
        LDMX4(al, wA + (EPI_WZL - EPI_WZH) + kk * 32 + laneA);
#pragma unroll
        for (int jp = 0; jp < 4; jp++) {
            uint32_t ba = sb + EPI_YH + (uint32_t)(jp * (16 * 272) + kk * 32) + laneB;
            uint32_t bh[4], bl[4];
            LDMX4(bh, ba);
            LDMX4(bl, ba + (EPI_YL - EPI_YH));
            MMA16816(acc[2 * jp],     ah, bh[0], bh[1]);
            MMA16816(acc[2 * jp + 1], ah, bh[2], bh[3]);
            MMA16816(acc[2 * jp],     al, bh[0], bh[1]);
            MMA16816(acc[2 * jp + 1], al, bh[2], bh[3]);
            MMA16816(acc[2 * jp],     ah, bl[0], bl[1]);
            MMA16816(acc[2 * jp + 1], ah, bl[2], bl[3]);
        }
    }

    const size_t row0 = (size_t)(b * C_ + c0 + w * 16 + g) * NPOS + n0;
    const size_t row1 = row0 + (size_t)8 * NPOS;
#pragma unroll
    for (int j = 0; j < 8; j++) {
        int col = j * 8 + 2 * tq;
        float2 x0 = *(const float2*)(x + row0 + col);
        float2 x1 = *(const float2*)(x + row1 + col);
        *(float2*)(out + row0 + col) = make_float2(acc[j][0] + x0.x, acc[j][1] + x0.y);
        *(float2*)(out + row1 + col) = make_float2(acc[j][2] + x1.x, acc[j][3] + x1.y);
    }
}

// =============================================================================
extern "C" void kernel_launch(void* const* d_in, const int* in_sizes, int n_in,
                              void* d_out, int out_size)
{
    const float* x      = (const float*)d_in[0];
    const float* Wg     = (const float*)d_in[1];
    const float* Wtheta = (const float*)d_in[2];
    const float* Wphi   = (const float*)d_in[3];
    const float* Wz     = (const float*)d_in[4];
    float* out = (float*)d_out;

    cudaFuncSetAttribute(proj_mma_kernel, cudaFuncAttributeMaxDynamicSharedMemorySize, PROJ_SMEM);
    cudaFuncSetAttribute(flash_kernel, cudaFuncAttributeMaxDynamicSharedMemorySize, FLASH_SMEM);
    cudaFuncSetAttribute(epi_kernel, cudaFuncAttributeMaxDynamicSharedMemorySize, EPI_SMEM);

    split_x_kernel<<<6272, 256>>>(x);
    split_w_kernel<<<dim3(32, 3), 256>>>(Wtheta, Wphi, Wg);
    proj_mma_kernel<<<dim3(NPOS / 128, 3, B_), 256, PROJ_SMEM>>>();
    flash_kernel<<<dim3(NPOS / 128, NSPLIT, B_), 256, FLASH_SMEM>>>();
    epi_kernel<<<dim3(NPOS / 64, C_ / 128, B_), 256, EPI_SMEM>>>(Wz, x, out);
}

// round 15
// speedup vs baseline: 1.0314x; 1.0023x over previous
#include <cuda_runtime.h>
#include <cuda_bf16.h>
#include <cstdint>
#include <math.h>

#define B_    4
#define C_    256
#define D_    128
#define NPOS  6272
#define BN    64
#define NSPLIT 3
#define MFIX  80.0f

// ---------------- scratch (static __device__, no allocation) ----------------
__device__ __nv_bfloat16 g_xh[(size_t)B_ * C_ * NPOS];
__device__ __nv_bfloat16 g_xl[(size_t)B_ * C_ * NPOS];
__device__ __nv_bfloat16 g_wh[3 * D_ * C_];
__device__ __nv_bfloat16 g_wl[3 * D_ * C_];
__device__ __nv_bfloat16 g_qh[(size_t)B_ * NPOS * D_];
__device__ __nv_bfloat16 g_ql[(size_t)B_ * NPOS * D_];
__device__ __nv_bfloat16 g_kh[(size_t)B_ * NPOS * D_];
__device__ __nv_bfloat16 g_kl[(size_t)B_ * NPOS * D_];
__device__ __nv_bfloat16 g_vth[(size_t)B_ * D_ * NPOS];  // V^T [b][d][n]
__device__ __nv_bfloat16 g_vtl[(size_t)B_ * D_ * NPOS];
__device__ float g_yp[NSPLIT][(size_t)B_ * NPOS * D_];   // unnormalized partial O
__device__ float g_lp[NSPLIT][(size_t)B_ * NPOS];        // partial l

// ======================= helpers ==================
__device__ __forceinline__ uint32_t smem_to_u32(const void* p) {
    uint32_t a;
    asm("{ .reg .u64 t; cvta.to.shared.u64 t, %1; cvt.u32.u64 %0, t; }" : "=r"(a) : "l"(p));
    return a;
}
__device__ __forceinline__ void cpa16(uint32_t s, const void* g) {
    asm volatile("cp.async.cg.shared.global [%0], [%1], 16;" :: "r"(s), "l"(g));
}
#define CP_COMMIT() asm volatile("cp.async.commit_group;" ::: "memory")

// D = A(16x16 bf16, row) * B(16x8 bf16, col) + D (f32)
#define MMA16816(c, a, b0_, b1_) \
    asm volatile("mma.sync.aligned.m16n8k16.row.col.f32.bf16.bf16.f32 " \
        "{%0,%1,%2,%3}, {%4,%5,%6,%7}, {%8,%9}, {%0,%1,%2,%3};" \
        : "+f"((c)[0]), "+f"((c)[1]), "+f"((c)[2]), "+f"((c)[3]) \
        : "r"((a)[0]), "r"((a)[1]), "r"((a)[2]), "r"((a)[3]), "r"(b0_), "r"(b1_))

#define LDMX4(rr, addr) \
    asm volatile("ldmatrix.sync.aligned.m8n8.x4.shared.b16 {%0,%1,%2,%3}, [%4];" \
        : "=r"((rr)[0]), "=r"((rr)[1]), "=r"((rr)[2]), "=r"((rr)[3]) : "r"(addr))
#define LDMX4T(rr, addr) \
    asm volatile("ldmatrix.sync.aligned.m8n8.x4.trans.shared.b16 {%0,%1,%2,%3}, [%4];" \
        : "=r"((rr)[0]), "=r"((rr)[1]), "=r"((rr)[2]), "=r"((rr)[3]) : "r"(addr))

// split f32 pair -> hi(trunc) packed bf16x2 (a in low half) + lo(rn) packed
__device__ __forceinline__ uint32_t packsplit(float a, float b, uint32_t& lo) {
    uint32_t ua = __float_as_uint(a), ub = __float_as_uint(b);
    float r0 = a - __uint_as_float(ua & 0xFFFF0000u);
    float r1 = b - __uint_as_float(ub & 0xFFFF0000u);
    asm("cvt.rn.bf16x2.f32 %0, %1, %2;" : "=r"(lo) : "f"(r1), "f"(r0));
    return (ua >> 16) | (ub & 0xFFFF0000u);
}

// trunc-pack only, and return the truncated hi values as floats (for l = Σph)
__device__ __forceinline__ uint32_t packtrunc(float a, float b, float& ha, float& hb) {
    uint32_t ua = __float_as_uint(a), ub = __float_as_uint(b);
    ha = __uint_as_float(ua & 0xFFFF0000u);
    hb = __uint_as_float(ub & 0xFFFF0000u);
    return (ua >> 16) | (ub & 0xFFFF0000u);
}

// =============================================================================
// Kernel 0a: split x -> bf16 hi/lo.
// =============================================================================
__global__ void __launch_bounds__(256) split_x_kernel(const float* __restrict__ x)
{
    size_t i = ((size_t)blockIdx.x * 256 + threadIdx.x) * 4;
    float4 v = *(const float4*)(x + i);
    uint32_t l0, l1;
    uint32_t h0 = packsplit(v.x, v.y, l0);
    uint32_t h1 = packsplit(v.z, v.w, l1);
    *(uint2*)((uint16_t*)g_xh + i) = make_uint2(h0, h1);
    *(uint2*)((uint16_t*)g_xl + i) = make_uint2(l0, l1);
}

// Kernel 0b: split W{theta,phi,g} -> bf16 hi/lo.
__global__ void __launch_bounds__(256) split_w_kernel(
    const float* __restrict__ Wt, const float* __restrict__ Wp,
    const float* __restrict__ Wg_)
{
    int which = blockIdx.y;
    const float* W = (which == 0) ? Wt : (which == 1) ? Wp : Wg_;
    size_t i = ((size_t)blockIdx.x * 256 + threadIdx.x) * 4;
    float4 v = *(const float4*)(W + i);
    uint32_t l0, l1;
    uint32_t h0 = packsplit(v.x, v.y, l0);
    uint32_t h1 = packsplit(v.z, v.w, l1);
    size_t o = (size_t)which * (D_ * C_) + i;
    *(uint2*)((uint16_t*)g_wh + o) = make_uint2(h0, h1);
    *(uint2*)((uint16_t*)g_wl + o) = make_uint2(l0, l1);
}

// =============================================================================
// Kernel 1: proj via mma.sync (3-pass bf16 emulation).  k-chunk 32, 8 iters,
// 2-stage pipeline, 2 CTAs/SM (75.8 KB/CTA, <=128 regs).
// grid (49, 3, B), 256 thr.  which: 0=theta->Q, 1=phi->K, 2=g->V^T.
// =============================================================================
#define PSTG 37888
#define PROJ_SMEM (2 * PSTG)   // 75776

__device__ __forceinline__ void proj_ld(uint32_t sb, int s, int b, int which,
                                        int c0, int n0, int tid)
{
    uint32_t st = sb + (uint32_t)s * PSTG;
#pragma unroll
    for (int i = 0; i < 2; i++) {
        int ch = tid + i * 256;
        int r = ch >> 4, c16 = ch & 15;
        size_t src = ((size_t)(b * C_ + c0 + r)) * NPOS + n0 + c16 * 8;
        uint32_t dst = (uint32_t)(r * 272 + c16 * 16);
        cpa16(st + dst, (const char*)g_xh + src * 2);
        cpa16(st + 8704 + dst, (const char*)g_xl + src * 2);
    }
#pragma unroll
    for (int i = 0; i < 2; i++) {
        int ch = tid + i * 256;
        int r = ch >> 2, c16 = ch & 3;
        size_t src = (size_t)which * (D_ * C_) + (size_t)r * C_ + c0 + c16 * 8;
        uint32_t dst = (uint32_t)(r * 80 + c16 * 16);
        cpa16(st + 17408 + dst, (const char*)g_wh + src * 2);
        cpa16(st + 27648 + dst, (const char*)g_wl + src * 2);
    }
}

__global__ void __launch_bounds__(256, 2) proj_mma_kernel()
{
    extern __shared__ char smem[];
    uint32_t sb = smem_to_u32(smem);
    const int tid = threadIdx.x;
    const int w = tid >> 5, lane = tid & 31;
    const int g = lane >> 2, tq = lane & 3;
    const int b = blockIdx.z, which = blockIdx.y;
    const int n0 = blockIdx.x * 128;

    proj_ld(sb, 0, b, which, 0, n0, tid);
    CP_COMMIT();
    proj_ld(sb, 1, b, which, 32, n0, tid);
    CP_COMMIT();

    float acc[16][4];
#pragma unroll
    for (int j = 0; j < 16; j++)
#pragma unroll
        for (int e = 0; e < 4; e++) acc[j][e] = 0.f;

    const int l7 = lane & 7, lb3 = (lane >> 3) & 1, lb4 = lane >> 4;
    const uint32_t laneAX = (uint32_t)((l7 + lb4 * 8) * 272 + (lb3 * 8) * 2);
    const uint32_t laneBW = (uint32_t)((lb4 * 8 + l7) * 80 + lb3 * 16);
    const uint32_t laneAW = (uint32_t)((l7 + lb3 * 8) * 80 + lb4 * 16);
    const uint32_t laneBX = (uint32_t)((l7 + lb3 * 8) * 272 + (lb4 * 8) * 2);

    int st = 0;
    for (int it = 0; it < 8; it++) {
        if (it + 1 < 8) {
            asm volatile("cp.async.wait_group 1;" ::: "memory");
        } else {
            asm volatile("cp.async.wait_group 0;" ::: "memory");
        }
        __syncthreads();

        const uint32_t XH = sb + (uint32_t)st * PSTG;
        const uint32_t WH = XH + 17408;

        if (which < 2) {
#pragma unroll
            for (int kk = 0; kk < 2; kk++) {
                uint32_t axh[4], axl[4];
                uint32_t aaddr = XH + (uint32_t)(kk * 16 * 272) + (uint32_t)(w * 16 * 2) + laneAX;
                LDMX4T(axh, aaddr);
                LDMX4T(axl, aaddr + 8704);
#pragma unroll
                for (int jp = 0; jp < 8; jp++) {
                    uint32_t baddr = WH + (uint32_t)(jp * 16 * 80 + kk * 32) + laneBW;
                    uint32_t bh[4], bl[4];
                    LDMX4(bh, baddr);
                    LDMX4(bl, baddr + 10240);
                    MMA16816(acc[2 * jp],     axh, bh[0], bh[1]);
                    MMA16816(acc[2 * jp + 1], axh, bh[2], bh[3]);
                    MMA16816(acc[2 * jp],     axl, bh[0], bh[1]);
                    MMA16816(acc[2 * jp + 1], axl, bh[2], bh[3]);
                    MMA16816(acc[2 * jp],     axh, bl[0], bl[1]);
                    MMA16816(acc[2 * jp + 1], axh, bl[2], bl[3]);
                }
            }
        } else {
#pragma unroll
            for (int kk = 0; kk < 2; kk++) {
                uint32_t awh[4], awl[4];
                uint32_t aaddr = WH + (uint32_t)(w * 16 * 80 + kk * 32) + laneAW;
                LDMX4(awh, aaddr);
                LDMX4(awl, aaddr + 10240);
#pragma unroll
                for (int jp = 0; jp < 8; jp++) {
                    uint32_t baddr = XH + (uint32_t)(kk * 16 * 272) + (uint32_t)(jp * 16 * 2) + laneBX;
                    uint32_t bxh[4], bxl[4];
                    LDMX4T(bxh, baddr);
                    LDMX4T(bxl, baddr + 8704);
                    MMA16816(acc[2 * jp],     awh, bxh[0], bxh[1]);
                    MMA16816(acc[2 * jp + 1], awh, bxh[2], bxh[3]);
                    MMA16816(acc[2 * jp],     awl, bxh[0], bxh[1]);
                    MMA16816(acc[2 * jp + 1], awl, bxh[2], bxh[3]);
                    MMA16816(acc[2 * jp],     awh, bxl[0], bxl[1]);
                    MMA16816(acc[2 * jp + 1], awh, bxl[2], bxl[3]);
                }
            }
        }

        __syncthreads();
        if (it + 2 < 8) {
            proj_ld(sb, st, b, which, (it + 2) * 32, n0, tid);
            CP_COMMIT();
        }
        st ^= 1;
    }

    if (which < 2) {
        uint16_t* hi = (uint16_t*)((which == 0) ? g_qh : g_kh);
        uint16_t* lo = (uint16_t*)((which == 0) ? g_ql : g_kl);
        size_t row0 = ((size_t)b * NPOS + n0 + w * 16 + g) * D_;
        size_t row1 = row0 + (size_t)8 * D_;
#pragma unroll
        for (int j = 0; j < 16; j++) {
            int col = j * 8 + 2 * tq;
            uint32_t lo0, lo1;
            uint32_t h0 = packsplit(acc[j][0], acc[j][1], lo0);
            uint32_t h1 = packsplit(acc[j][2], acc[j][3], lo1);
            *(uint32_t*)(hi + row0 + col) = h0;
            *(uint32_t*)(lo + row0 + col) = lo0;
            *(uint32_t*)(hi + row1 + col) = h1;
            *(uint32_t*)(lo + row1 + col) = lo1;
        }
    } else {
        uint16_t* hi = (uint16_t*)g_vth;
        uint16_t* lo = (uint16_t*)g_vtl;
        size_t row0 = ((size_t)b * D_ + w * 16 + g) * NPOS + n0;
        size_t row1 = row0 + (size_t)8 * NPOS;
#pragma unroll
        for (int j = 0; j < 16; j++) {
            int col = j * 8 + 2 * tq;
            uint32_t lo0, lo1;
            uint32_t h0 = packsplit(acc[j][0], acc[j][1], lo0);
            uint32_t h1 = packsplit(acc[j][2], acc[j][3], lo1);
            *(uint32_t*)(hi + row0 + col) = h0;
            *(uint32_t*)(lo + row0 + col) = lo0;
            *(uint32_t*)(hi + row1 + col) = h1;
            *(uint32_t*)(lo + row1 + col) = lo1;
        }
    }
}

// =============================================================================
// Kernel 2: flash attention (round-11: Q hi/lo in SMEM, 2-stage K/V,
// S 3-pass + PV 2-pass self-normalized with l = Σ truncated-P).  UNCHANGED.
// =============================================================================
#define SZ_Q    34816
#define OFF_KV  (2 * SZ_Q)
#define SZ_KHL  17408
#define SZ_KST  (2 * SZ_KHL)
#define SZ_VHL  18432
#define SZ_VST  (2 * SZ_VHL)
#define SZ_STAGE (SZ_KST + SZ_VST)
#define FLASH_SMEM (OFF_KV + 2 * SZ_STAGE)   // 212992

__device__ __forceinline__ void ld_stage(uint32_t sb, int st, int b, int kt, int tid)
{
    const char* kh = (const char*)(g_kh + ((size_t)b * NPOS + (size_t)kt * BN) * D_);
    const char* kl = (const char*)(g_kl + ((size_t)b * NPOS + (size_t)kt * BN) * D_);
    uint32_t kb = sb + OFF_KV + st * SZ_STAGE;
#pragma unroll
    for (int i = 0; i < 4; i++) {
        int ch = tid + i * 256;
        int r = ch >> 4, c = ch & 15;
        uint32_t off = (uint32_t)(r * 272 + c * 16);
        size_t go = (size_t)r * 256 + c * 16;
        cpa16(kb + off, kh + go);
        cpa16(kb + SZ_KHL + off, kl + go);
    }
    const char* vh = (const char*)(g_vth + (size_t)b * D_ * NPOS + (size_t)kt * BN);
    const char* vl = (const char*)(g_vtl + (size_t)b * D_ * NPOS + (size_t)kt * BN);
    uint32_t vb = kb + SZ_KST;
#pragma unroll
    for (int i = 0; i < 4; i++) {
        int ch = tid + i * 256;
        int r = ch >> 3, c = ch & 7;
        uint32_t off = (uint32_t)(r * 144 + c * 16);
        size_t go = (size_t)r * (NPOS * 2) + c * 16;
        cpa16(vb + off, vh + go);
        cpa16(vb + SZ_VHL + off, vl + go);
    }
}

// S for one chunk-pair p (kv cols 32p .. 32p+31): Q frags from smem.
__device__ __forceinline__ void s_pair(float (&s)[2][2][4], uint32_t Kst, int p,
                                       uint32_t qbase, uint32_t laneK)
{
#pragma unroll
    for (int jc = 0; jc < 2; jc++)
#pragma unroll
        for (int h = 0; h < 2; h++)
#pragma unroll
            for (int e = 0; e < 4; e++) s[jc][h][e] = 0.f;
#pragma unroll
    for (int kk = 0; kk < 8; kk++) {
        uint32_t qh[4], ql[4];
        LDMX4(qh, qbase + kk * 32);
        LDMX4(ql, qbase + kk * 32 + SZ_Q);
#pragma unroll
        for (int jc = 0; jc < 2; jc++) {
            int jp = 2 * p + jc;
            uint32_t addr = Kst + (uint32_t)(jp * (16 * 272) + kk * 32) + laneK;
            uint32_t bh[4], bl[4];
            LDMX4(bh, addr);
            LDMX4(bl, addr + SZ_KHL);
            MMA16816(s[jc][0], qh, bh[0], bh[1]);
            MMA16816(s[jc][1], qh, bh[2], bh[3]);
            MMA16816(s[jc][0], ql, bh[0], bh[1]);
            MMA16816(s[jc][1], ql, bh[2], bh[3]);
            MMA16816(s[jc][0], qh, bl[0], bl[1]);
            MMA16816(s[jc][1], qh, bl[2], bl[3]);
        }
    }
}

// softmax of one 16-col chunk (P truncated to bf16; l accumulates the SAME
// truncated values) + its 2-pass PV MMAs (Ph*Vh + Ph*Vl).
__device__ __forceinline__ void sm_pv(const float (&sc)[2][4], int jp,
                                      uint32_t Vst, uint32_t laneV,
                                      float (&oacc)[16][4], float& lr0, float& lr1)
{
    uint32_t phj[4];
    {
        float h0, h1;
        float p0 = __expf(sc[0][0] - MFIX), p1 = __expf(sc[0][1] - MFIX);
        float p2 = __expf(sc[0][2] - MFIX), p3 = __expf(sc[0][3] - MFIX);
        phj[0] = packtrunc(p0, p1, h0, h1); lr0 += h0 + h1;
        phj[1] = packtrunc(p2, p3, h0, h1); lr1 += h0 + h1;
        float q0 = __expf(sc[1][0] - MFIX), q1 = __expf(sc[1][1] - MFIX);
        float q2 = __expf(sc[1][2] - MFIX), q3 = __expf(sc[1][3] - MFIX);
        phj[2] = packtrunc(q0, q1, h0, h1); lr0 += h0 + h1;
        phj[3] = packtrunc(q2, q3, h0, h1); lr1 += h0 + h1;
    }
#pragma unroll
    for (int j2 = 0; j2 < 8; j2++) {
        uint32_t addr = Vst + (uint32_t)(j2 * (16 * 144) + jp * 32) + laneV;
        uint32_t vh_[4], vl_[4];
        LDMX4(vh_, addr);
        LDMX4(vl_, addr + SZ_VHL);
        MMA16816(oacc[2 * j2],     phj, vh_[0], vh_[1]);
        MMA16816(oacc[2 * j2 + 1], phj, vh_[2], vh_[3]);
        MMA16816(oacc[2 * j2],     phj, vl_[0], vl_[1]);
        MMA16816(oacc[2 * j2 + 1], phj, vl_[2], vl_[3]);
    }
}

__global__ void __launch_bounds__(256, 1) flash_kernel()
{
    extern __shared__ char smem[];
    uint32_t sb = smem_to_u32(smem);
    const int tid = threadIdx.x;
    const int w = tid >> 5, lane = tid & 31;
    const int g = lane >> 2, tq = lane & 3;
    const int q0 = blockIdx.x * 128;
    const int split = blockIdx.y;
    const int b = blockIdx.z;
    const int ks = (split * 98) / 3;
    const int ke = ((split + 1) * 98) / 3;

    // prologue: Q (hi/lo) + stage0 in group0; stage1 in group1
    {
        const char* gqh = (const char*)(g_qh + ((size_t)b * NPOS + q0) * D_);
        const char* gql = (const char*)(g_ql + ((size_t)b * NPOS + q0) * D_);
#pragma unroll
        for (int i = 0; i < 8; i++) {
            int ch = tid + i * 256;
            int r = ch >> 4, c = ch & 15;
            uint32_t dst = (uint32_t)(r * 272 + c * 16);
            size_t src = (size_t)r * 256 + c * 16;
            cpa16(sb + dst, gqh + src);
            cpa16(sb + SZ_Q + dst, gql + src);
        }
    }
    ld_stage(sb, 0, b, ks, tid);
    CP_COMMIT();
    ld_stage(sb, 1, b, ks + 1, tid);
    CP_COMMIT();

    float oacc[16][4];
#pragma unroll
    for (int j = 0; j < 16; j++)
#pragma unroll
        for (int e = 0; e < 4; e++) oacc[j][e] = 0.f;
    float lr0 = 0.f, lr1 = 0.f;

    const int r8 = lane & 7, half = (lane >> 3) & 1, jjo = lane >> 4;
    const uint32_t laneK = (uint32_t)((jjo * 8 + r8) * 272 + half * 16);
    const uint32_t laneV = (uint32_t)((jjo * 8 + r8) * 144 + half * 16);
    const uint32_t qbase = sb + (uint32_t)((w * 16 + half * 8 + r8) * 272 + jjo * 16);

    int st = 0;
    for (int t = ks; t < ke; t++) {
        if (t + 1 < ke) {
            asm volatile("cp.async.wait_group 1;" ::: "memory");
        } else {
            asm volatile("cp.async.wait_group 0;" ::: "memory");
        }
        __syncthreads();

        const uint32_t Kst = sb + OFF_KV + st * SZ_STAGE;
        const uint32_t Vst = Kst + SZ_KST;

        float sA[2][2][4], sB[2][2][4];
        s_pair(sA, Kst, 0, qbase, laneK);
        s_pair(sB, Kst, 1, qbase, laneK);
        sm_pv(sA[0], 0, Vst, laneV, oacc, lr0, lr1);
        sm_pv(sA[1], 1, Vst, laneV, oacc, lr0, lr1);
        sm_pv(sB[0], 2, Vst, laneV, oacc, lr0, lr1);
        sm_pv(sB[1], 3, Vst, laneV, oacc, lr0, lr1);

        __syncthreads();
        if (t + 2 < ke) {
            ld_stage(sb, st, b, t + 2, tid);
            CP_COMMIT();
        }
        st ^= 1;
    }

    lr0 += __shfl_xor_sync(0xffffffffu, lr0, 1);
    lr0 += __shfl_xor_sync(0xffffffffu, lr0, 2);
    lr1 += __shfl_xor_sync(0xffffffffu, lr1, 1);
    lr1 += __shfl_xor_sync(0xffffffffu, lr1, 2);
    if (tq == 0) {
        size_t base = (size_t)b * NPOS + q0 + w * 16;
        g_lp[split][base + g] = lr0;
        g_lp[split][base + g + 8] = lr1;
    }

    float* yd = g_yp[split] + ((size_t)b * NPOS + q0 + w * 16) * D_;
#pragma unroll
    for (int j = 0; j < 16; j++) {
        *(float2*)(yd + (size_t)g * D_ + j * 8 + 2 * tq) = make_float2(oacc[j][0], oacc[j][1]);
        *(float2*)(yd + (size_t)(g + 8) * D_ + j * 8 + 2 * tq) = make_float2(oacc[j][2], oacc[j][3]);
    }
}

// =============================================================================
// Kernel 3 (mma): out[b][c][n] = x + Wz @ (Σ_s y_s / L).  n-tile 64, 2 CTAs/SM.
// =============================================================================
#define EPI_WZH  0
#define EPI_WZL  34816
#define EPI_YH   69632
#define EPI_YL   87040
#define EPI_LINV 104448
#define EPI_SMEM (EPI_LINV + 256)

__global__ void __launch_bounds__(256, 2) epi_kernel(
    const float* __restrict__ Wz, const float* __restrict__ x, float* __restrict__ out)
{
    extern __shared__ char smem[];
    uint32_t sb = smem_to_u32(smem);
    const int tid = threadIdx.x;
    const int w = tid >> 5, lane = tid & 31;
    const int g = lane >> 2, tq = lane & 3;
    const int b = blockIdx.z;
    const int c0 = blockIdx.y * 128;
    const int n0 = blockIdx.x * 64;

    float* linv = (float*)(smem + EPI_LINV);
    if (tid < 64) {
        size_t li = (size_t)b * NPOS + n0 + tid;
        linv[tid] = 1.f / (g_lp[0][li] + g_lp[1][li] + g_lp[2][li]);
    }
    __syncthreads();

    for (int v = tid; v < 128 * 32; v += 256) {
        int r = v >> 5, c = v & 31;
        float4 wv = *(const float4*)(Wz + (size_t)(c0 + r) * D_ + 4 * c);
        uint32_t l0, l1;
        uint32_t h0 = packsplit(wv.x, wv.y, l0);
        uint32_t h1 = packsplit(wv.z, wv.w, l1);
        *(uint2*)(smem + EPI_WZH + r * 272 + c * 8) = make_uint2(h0, h1);
        *(uint2*)(smem + EPI_WZL + r * 272 + c * 8) = make_uint2(l0, l1);
    }
    {
        const float* y0 = g_yp[0] + ((size_t)b * NPOS + n0) * D_;
        const float* y1 = g_yp[1] + ((size_t)b * NPOS + n0) * D_;
        const float* y2 = g_yp[2] + ((size_t)b * NPOS + n0) * D_;
        for (int v = tid; v < 64 * 32; v += 256) {
            int r = v >> 5, c = v & 31;
            size_t o = (size_t)r * D_ + 4 * c;
            float4 a = *(const float4*)(y0 + o);
            float4 bb = *(const float4*)(y1 + o);
            float4 cc = *(const float4*)(y2 + o);
            float s = linv[r];
            float vx = (a.x + bb.x + cc.x) * s;
            float vy = (a.y + bb.y + cc.y) * s;
            float vz = (a.z + bb.z + cc.z) * s;
            float vw = (a.w + bb.w + cc.w) * s;
            uint32_t l0, l1;
            uint32_t h0 = packsplit(vx, vy, l0);
            uint32_t h1 = packsplit(vz, vw, l1);
            *(uint2*)(smem + EPI_YH + r * 272 + c * 8) = make_uint2(h0, h1);
            *(uint2*)(smem + EPI_YL + r * 272 + c * 8) = make_uint2(l0, l1);
        }
    }
    __syncthreads();

    float acc[8][4];
#pragma unroll
    for (int j = 0; j < 8; j++)
#pragma unroll
        for (int e = 0; e < 4; e++) acc[j][e] = 0.f;

    const int r8 = lane & 7;
    const uint32_t laneA = (uint32_t)((((lane >> 3) & 1) * 8 + r8) * 272 + (lane >> 4) * 16);
    const uint32_t laneB = (uint32_t)(((lane >> 4) * 8 + r8) * 272 + ((lane >> 3) & 1) * 16);
    const uint32_t wA = sb + EPI_WZH + (uint32_t)(w * 16 * 272);

#pragma unroll
    for (int kk = 0; kk < 8; kk++) {
        uint32_t ah[4], al[4];
        LDMX4(ah, wA + kk * 32 + laneA);
        LDMX4(al, wA + (EPI_WZL - EPI_WZH) + kk * 32 + laneA);
#pragma unroll
        for (int jp = 0; jp < 4; jp++) {
            uint32_t ba = sb + EPI_YH + (uint32_t)(jp * (16 * 272) + kk * 32) + laneB;
            uint32_t bh[4], bl[4];
            LDMX4(bh, ba);
            LDMX4(bl, ba + (EPI_YL - EPI_YH));
            MMA16816(acc[2 * jp],     ah, bh[0], bh[1]);
            MMA16816(acc[2 * jp + 1], ah, bh[2], bh[3]);
            MMA16816(acc[2 * jp],     al, bh[0], bh[1]);
            MMA16816(acc[2 * jp + 1], al, bh[2], bh[3]);
            MMA16816(acc[2 * jp],     ah, bl[0], bl[1]);
            MMA16816(acc[2 * jp + 1], ah, bl[2], bl[3]);
        }
    }

    const size_t row0 = (size_t)(b * C_ + c0 + w * 16 + g) * NPOS + n0;
    const size_t row1 = row0 + (size_t)8 * NPOS;
#pragma unroll
    for (int j = 0; j < 8; j++) {
        int col = j * 8 + 2 * tq;
        float2 x0 = *(const float2*)(x + row0 + col);
        float2 x1 = *(const float2*)(x + row1 + col);
        *(float2*)(out + row0 + col) = make_float2(acc[j][0] + x0.x, acc[j][1] + x0.y);
        *(float2*)(out + row1 + col) = make_float2(acc[j][2] + x1.x, acc[j][3] + x1.y);
    }
}

// =============================================================================
extern "C" void kernel_launch(void* const* d_in, const int* in_sizes, int n_in,
                              void* d_out, int out_size)
{
    const float* x      = (const float*)d_in[0];
    const float* Wg     = (const float*)d_in[1];
    const float* Wtheta = (const float*)d_in[2];
    const float* Wphi   = (const float*)d_in[3];
    const float* Wz     = (const float*)d_in[4];
    float* out = (float*)d_out;

    cudaFuncSetAttribute(proj_mma_kernel, cudaFuncAttributeMaxDynamicSharedMemorySize, PROJ_SMEM);
    cudaFuncSetAttribute(flash_kernel, cudaFuncAttributeMaxDynamicSharedMemorySize, FLASH_SMEM);
    cudaFuncSetAttribute(epi_kernel, cudaFuncAttributeMaxDynamicSharedMemorySize, EPI_SMEM);

    split_x_kernel<<<6272, 256>>>(x);
    split_w_kernel<<<dim3(32, 3), 256>>>(Wtheta, Wphi, Wg);
    proj_mma_kernel<<<dim3(NPOS / 128, 3, B_), 256, PROJ_SMEM>>>();
    flash_kernel<<<dim3(NPOS / 128, NSPLIT, B_), 256, FLASH_SMEM>>>();
    epi_kernel<<<dim3(NPOS / 64, C_ / 128, B_), 256, EPI_SMEM>>>(Wz, x, out);
}

// round 17
// speedup vs baseline: 1.0322x; 1.0007x over previous
#include <cuda_runtime.h>
#include <cuda_bf16.h>
#include <cstdint>
#include <math.h>

#define B_    4
#define C_    256
#define D_    128
#define NPOS  6272
#define BN    64
#define NSPLIT 3
#define MFIX  80.0f

// ---------------- scratch (static __device__, no allocation) ----------------
__device__ __nv_bfloat16 g_xh[(size_t)B_ * C_ * NPOS];
__device__ __nv_bfloat16 g_xl[(size_t)B_ * C_ * NPOS];
__device__ __nv_bfloat16 g_wh[3 * D_ * C_];
__device__ __nv_bfloat16 g_wl[3 * D_ * C_];
__device__ __nv_bfloat16 g_qh[(size_t)B_ * NPOS * D_];
__device__ __nv_bfloat16 g_ql[(size_t)B_ * NPOS * D_];
__device__ __nv_bfloat16 g_kh[(size_t)B_ * NPOS * D_];
__device__ __nv_bfloat16 g_kl[(size_t)B_ * NPOS * D_];
__device__ __nv_bfloat16 g_vth[(size_t)B_ * D_ * NPOS];  // V^T [b][d][n]
__device__ __nv_bfloat16 g_vtl[(size_t)B_ * D_ * NPOS];
__device__ float g_yp[NSPLIT][(size_t)B_ * NPOS * D_];   // unnormalized partial O
__device__ float g_lp[NSPLIT][(size_t)B_ * NPOS];        // partial l

// ======================= helpers ==================
__device__ __forceinline__ uint32_t smem_to_u32(const void* p) {
    uint32_t a;
    asm("{ .reg .u64 t; cvta.to.shared.u64 t, %1; cvt.u32.u64 %0, t; }" : "=r"(a) : "l"(p));
    return a;
}
__device__ __forceinline__ void cpa16(uint32_t s, const void* g) {
    asm volatile("cp.async.cg.shared.global [%0], [%1], 16;" :: "r"(s), "l"(g));
}
#define CP_COMMIT() asm volatile("cp.async.commit_group;" ::: "memory")

// D = A(16x16 bf16, row) * B(16x8 bf16, col) + D (f32)
#define MMA16816(c, a, b0_, b1_) \
    asm volatile("mma.sync.aligned.m16n8k16.row.col.f32.bf16.bf16.f32 " \
        "{%0,%1,%2,%3}, {%4,%5,%6,%7}, {%8,%9}, {%0,%1,%2,%3};" \
        : "+f"((c)[0]), "+f"((c)[1]), "+f"((c)[2]), "+f"((c)[3]) \
        : "r"((a)[0]), "r"((a)[1]), "r"((a)[2]), "r"((a)[3]), "r"(b0_), "r"(b1_))

#define LDMX4(rr, addr) \
    asm volatile("ldmatrix.sync.aligned.m8n8.x4.shared.b16 {%0,%1,%2,%3}, [%4];" \
        : "=r"((rr)[0]), "=r"((rr)[1]), "=r"((rr)[2]), "=r"((rr)[3]) : "r"(addr))
#define LDMX4T(rr, addr) \
    asm volatile("ldmatrix.sync.aligned.m8n8.x4.trans.shared.b16 {%0,%1,%2,%3}, [%4];" \
        : "=r"((rr)[0]), "=r"((rr)[1]), "=r"((rr)[2]), "=r"((rr)[3]) : "r"(addr))

// split f32 pair -> hi(trunc) packed bf16x2 (a in low half) + lo(rn) packed
__device__ __forceinline__ uint32_t packsplit(float a, float b, uint32_t& lo) {
    uint32_t ua = __float_as_uint(a), ub = __float_as_uint(b);
    float r0 = a - __uint_as_float(ua & 0xFFFF0000u);
    float r1 = b - __uint_as_float(ub & 0xFFFF0000u);
    asm("cvt.rn.bf16x2.f32 %0, %1, %2;" : "=r"(lo) : "f"(r1), "f"(r0));
    return (ua >> 16) | (ub & 0xFFFF0000u);
}

// trunc-pack only, and return the truncated hi values as floats (for l = Σph)
__device__ __forceinline__ uint32_t packtrunc(float a, float b, float& ha, float& hb) {
    uint32_t ua = __float_as_uint(a), ub = __float_as_uint(b);
    ha = __uint_as_float(ua & 0xFFFF0000u);
    hb = __uint_as_float(ub & 0xFFFF0000u);
    return (ua >> 16) | (ub & 0xFFFF0000u);
}

// =============================================================================
// Kernel 0a: split x -> bf16 hi/lo.
// =============================================================================
__global__ void __launch_bounds__(256) split_x_kernel(const float* __restrict__ x)
{
    size_t i = ((size_t)blockIdx.x * 256 + threadIdx.x) * 4;
    float4 v = *(const float4*)(x + i);
    uint32_t l0, l1;
    uint32_t h0 = packsplit(v.x, v.y, l0);
    uint32_t h1 = packsplit(v.z, v.w, l1);
    *(uint2*)((uint16_t*)g_xh + i) = make_uint2(h0, h1);
    *(uint2*)((uint16_t*)g_xl + i) = make_uint2(l0, l1);
}

// Kernel 0b: split W{theta,phi,g} -> bf16 hi/lo.
__global__ void __launch_bounds__(256) split_w_kernel(
    const float* __restrict__ Wt, const float* __restrict__ Wp,
    const float* __restrict__ Wg_)
{
    int which = blockIdx.y;
    const float* W = (which == 0) ? Wt : (which == 1) ? Wp : Wg_;
    size_t i = ((size_t)blockIdx.x * 256 + threadIdx.x) * 4;
    float4 v = *(const float4*)(W + i);
    uint32_t l0, l1;
    uint32_t h0 = packsplit(v.x, v.y, l0);
    uint32_t h1 = packsplit(v.z, v.w, l1);
    size_t o = (size_t)which * (D_ * C_) + i;
    *(uint2*)((uint16_t*)g_wh + o) = make_uint2(h0, h1);
    *(uint2*)((uint16_t*)g_wl + o) = make_uint2(l0, l1);
}

// =============================================================================
// Kernel 1: proj via mma.sync (3-pass bf16 emulation).  k-chunk 32, 8 iters,
// 2-stage pipeline, 2 CTAs/SM (75.8 KB/CTA, <=128 regs).
// grid (49, 3, B), 256 thr.  which: 0=theta->Q, 1=phi->K, 2=g->V^T.
// =============================================================================
#define PSTG 37888
#define PROJ_SMEM (2 * PSTG)   // 75776

__device__ __forceinline__ void proj_ld(uint32_t sb, int s, int b, int which,
                                        int c0, int n0, int tid)
{
    uint32_t st = sb + (uint32_t)s * PSTG;
#pragma unroll
    for (int i = 0; i < 2; i++) {
        int ch = tid + i * 256;
        int r = ch >> 4, c16 = ch & 15;
        size_t src = ((size_t)(b * C_ + c0 + r)) * NPOS + n0 + c16 * 8;
        uint32_t dst = (uint32_t)(r * 272 + c16 * 16);
        cpa16(st + dst, (const char*)g_xh + src * 2);
        cpa16(st + 8704 + dst, (const char*)g_xl + src * 2);
    }
#pragma unroll
    for (int i = 0; i < 2; i++) {
        int ch = tid + i * 256;
        int r = ch >> 2, c16 = ch & 3;
        size_t src = (size_t)which * (D_ * C_) + (size_t)r * C_ + c0 + c16 * 8;
        uint32_t dst = (uint32_t)(r * 80 + c16 * 16);
        cpa16(st + 17408 + dst, (const char*)g_wh + src * 2);
        cpa16(st + 27648 + dst, (const char*)g_wl + src * 2);
    }
}

__global__ void __launch_bounds__(256, 2) proj_mma_kernel()
{
    extern __shared__ char smem[];
    uint32_t sb = smem_to_u32(smem);
    const int tid = threadIdx.x;
    const int w = tid >> 5, lane = tid & 31;
    const int g = lane >> 2, tq = lane & 3;
    const int b = blockIdx.z, which = blockIdx.y;
    const int n0 = blockIdx.x * 128;

    proj_ld(sb, 0, b, which, 0, n0, tid);
    CP_COMMIT();
    proj_ld(sb, 1, b, which, 32, n0, tid);
    CP_COMMIT();

    float acc[16][4];
#pragma unroll
    for (int j = 0; j < 16; j++)
#pragma unroll
        for (int e = 0; e < 4; e++) acc[j][e] = 0.f;

    const int l7 = lane & 7, lb3 = (lane >> 3) & 1, lb4 = lane >> 4;
    const uint32_t laneAX = (uint32_t)((l7 + lb4 * 8) * 272 + (lb3 * 8) * 2);
    const uint32_t laneBW = (uint32_t)((lb4 * 8 + l7) * 80 + lb3 * 16);
    const uint32_t laneAW = (uint32_t)((l7 + lb3 * 8) * 80 + lb4 * 16);
    const uint32_t laneBX = (uint32_t)((l7 + lb3 * 8) * 272 + (lb4 * 8) * 2);

    int st = 0;
    for (int it = 0; it < 8; it++) {
        if (it + 1 < 8) {
            asm volatile("cp.async.wait_group 1;" ::: "memory");
        } else {
            asm volatile("cp.async.wait_group 0;" ::: "memory");
        }
        __syncthreads();

        const uint32_t XH = sb + (uint32_t)st * PSTG;
        const uint32_t WH = XH + 17408;

        if (which < 2) {
#pragma unroll
            for (int kk = 0; kk < 2; kk++) {
                uint32_t axh[4], axl[4];
                uint32_t aaddr = XH + (uint32_t)(kk * 16 * 272) + (uint32_t)(w * 16 * 2) + laneAX;
                LDMX4T(axh, aaddr);
                LDMX4T(axl, aaddr + 8704);
#pragma unroll
                for (int jp = 0; jp < 8; jp++) {
                    uint32_t baddr = WH + (uint32_t)(jp * 16 * 80 + kk * 32) + laneBW;
                    uint32_t bh[4], bl[4];
                    LDMX4(bh, baddr);
                    LDMX4(bl, baddr + 10240);
                    MMA16816(acc[2 * jp],     axh, bh[0], bh[1]);
                    MMA16816(acc[2 * jp + 1], axh, bh[2], bh[3]);
                    MMA16816(acc[2 * jp],     axl, bh[0], bh[1]);
                    MMA16816(acc[2 * jp + 1], axl, bh[2], bh[3]);
                    MMA16816(acc[2 * jp],     axh, bl[0], bl[1]);
                    MMA16816(acc[2 * jp + 1], axh, bl[2], bl[3]);
                }
            }
        } else {
#pragma unroll
            for (int kk = 0; kk < 2; kk++) {
                uint32_t awh[4], awl[4];
                uint32_t aaddr = WH + (uint32_t)(w * 16 * 80 + kk * 32) + laneAW;
                LDMX4(awh, aaddr);
                LDMX4(awl, aaddr + 10240);
#pragma unroll
                for (int jp = 0; jp < 8; jp++) {
                    uint32_t baddr = XH + (uint32_t)(kk * 16 * 272) + (uint32_t)(jp * 16 * 2) + laneBX;
                    uint32_t bxh[4], bxl[4];
                    LDMX4T(bxh, baddr);
                    LDMX4T(bxl, baddr + 8704);
                    MMA16816(acc[2 * jp],     awh, bxh[0], bxh[1]);
                    MMA16816(acc[2 * jp + 1], awh, bxh[2], bxh[3]);
                    MMA16816(acc[2 * jp],     awl, bxh[0], bxh[1]);
                    MMA16816(acc[2 * jp + 1], awl, bxh[2], bxh[3]);
                    MMA16816(acc[2 * jp],     awh, bxl[0], bxl[1]);
                    MMA16816(acc[2 * jp + 1], awh, bxl[2], bxl[3]);
                }
            }
        }

        __syncthreads();
        if (it + 2 < 8) {
            proj_ld(sb, st, b, which, (it + 2) * 32, n0, tid);
            CP_COMMIT();
        }
        st ^= 1;
    }

    if (which < 2) {
        uint16_t* hi = (uint16_t*)((which == 0) ? g_qh : g_kh);
        uint16_t* lo = (uint16_t*)((which == 0) ? g_ql : g_kl);
        size_t row0 = ((size_t)b * NPOS + n0 + w * 16 + g) * D_;
        size_t row1 = row0 + (size_t)8 * D_;
#pragma unroll
        for (int j = 0; j < 16; j++) {
            int col = j * 8 + 2 * tq;
            uint32_t lo0, lo1;
            uint32_t h0 = packsplit(acc[j][0], acc[j][1], lo0);
            uint32_t h1 = packsplit(acc[j][2], acc[j][3], lo1);
            *(uint32_t*)(hi + row0 + col) = h0;
            *(uint32_t*)(lo + row0 + col) = lo0;
            *(uint32_t*)(hi + row1 + col) = h1;
            *(uint32_t*)(lo + row1 + col) = lo1;
        }
    } else {
        uint16_t* hi = (uint16_t*)g_vth;
        uint16_t* lo = (uint16_t*)g_vtl;
        size_t row0 = ((size_t)b * D_ + w * 16 + g) * NPOS + n0;
        size_t row1 = row0 + (size_t)8 * NPOS;
#pragma unroll
        for (int j = 0; j < 16; j++) {
            int col = j * 8 + 2 * tq;
            uint32_t lo0, lo1;
            uint32_t h0 = packsplit(acc[j][0], acc[j][1], lo0);
            uint32_t h1 = packsplit(acc[j][2], acc[j][3], lo1);
            *(uint32_t*)(hi + row0 + col) = h0;
            *(uint32_t*)(lo + row0 + col) = lo0;
            *(uint32_t*)(hi + row1 + col) = h1;
            *(uint32_t*)(lo + row1 + col) = lo1;
        }
    }
}

// =============================================================================
// Kernel 2: flash attention (Q hi/lo in SMEM, 2-stage K/V,
// S 3-pass + PV 2-pass self-normalized with l = Σ truncated-P).
// =============================================================================
#define SZ_Q    34816
#define OFF_KV  (2 * SZ_Q)
#define SZ_KHL  17408
#define SZ_KST  (2 * SZ_KHL)
#define SZ_VHL  18432
#define SZ_VST  (2 * SZ_VHL)
#define SZ_STAGE (SZ_KST + SZ_VST)
#define FLASH_SMEM (OFF_KV + 2 * SZ_STAGE)   // 212992

__device__ __forceinline__ void ld_stage(uint32_t sb, int st, int b, int kt, int tid)
{
    const char* kh = (const char*)(g_kh + ((size_t)b * NPOS + (size_t)kt * BN) * D_);
    const char* kl = (const char*)(g_kl + ((size_t)b * NPOS + (size_t)kt * BN) * D_);
    uint32_t kb = sb + OFF_KV + st * SZ_STAGE;
#pragma unroll
    for (int i = 0; i < 4; i++) {
        int ch = tid + i * 256;
        int r = ch >> 4, c = ch & 15;
        uint32_t off = (uint32_t)(r * 272 + c * 16);
        size_t go = (size_t)r * 256 + c * 16;
        cpa16(kb + off, kh + go);
        cpa16(kb + SZ_KHL + off, kl + go);
    }
    const char* vh = (const char*)(g_vth + (size_t)b * D_ * NPOS + (size_t)kt * BN);
    const char* vl = (const char*)(g_vtl + (size_t)b * D_ * NPOS + (size_t)kt * BN);
    uint32_t vb = kb + SZ_KST;
#pragma unroll
    for (int i = 0; i < 4; i++) {
        int ch = tid + i * 256;
        int r = ch >> 3, c = ch & 7;
        uint32_t off = (uint32_t)(r * 144 + c * 16);
        size_t go = (size_t)r * (NPOS * 2) + c * 16;
        cpa16(vb + off, vh + go);
        cpa16(vb + SZ_VHL + off, vl + go);
    }
}

// S for one chunk-pair p (kv cols 32p .. 32p+31): Q frags from smem.
__device__ __forceinline__ void s_pair(float (&s)[2][2][4], uint32_t Kst, int p,
                                       uint32_t qbase, uint32_t laneK)
{
#pragma unroll
    for (int jc = 0; jc < 2; jc++)
#pragma unroll
        for (int h = 0; h < 2; h++)
#pragma unroll
            for (int e = 0; e < 4; e++) s[jc][h][e] = 0.f;
#pragma unroll
    for (int kk = 0; kk < 8; kk++) {
        uint32_t qh[4], ql[4];
        LDMX4(qh, qbase + kk * 32);
        LDMX4(ql, qbase + kk * 32 + SZ_Q);
#pragma unroll
        for (int jc = 0; jc < 2; jc++) {
            int jp = 2 * p + jc;
            uint32_t addr = Kst + (uint32_t)(jp * (16 * 272) + kk * 32) + laneK;
            uint32_t bh[4], bl[4];
            LDMX4(bh, addr);
            LDMX4(bl, addr + SZ_KHL);
            MMA16816(s[jc][0], qh, bh[0], bh[1]);
            MMA16816(s[jc][1], qh, bh[2], bh[3]);
            MMA16816(s[jc][0], ql, bh[0], bh[1]);
            MMA16816(s[jc][1], ql, bh[2], bh[3]);
            MMA16816(s[jc][0], qh, bl[0], bl[1]);
            MMA16816(s[jc][1], qh, bl[2], bl[3]);
        }
    }
}

// softmax of one 16-col chunk (P truncated to bf16; l accumulates the SAME
// truncated values) + its 2-pass PV MMAs (Ph*Vh + Ph*Vl).
__device__ __forceinline__ void sm_pv(const float (&sc)[2][4], int jp,
                                      uint32_t Vst, uint32_t laneV,
                                      float (&oacc)[16][4], float& lr0, float& lr1)
{
    uint32_t phj[4];
    {
        float h0, h1;
        float p0 = __expf(sc[0][0] - MFIX), p1 = __expf(sc[0][1] - MFIX);
        float p2 = __expf(sc[0][2] - MFIX), p3 = __expf(sc[0][3] - MFIX);
        phj[0] = packtrunc(p0, p1, h0, h1); lr0 += h0 + h1;
        phj[1] = packtrunc(p2, p3, h0, h1); lr1 += h0 + h1;
        float q0 = __expf(sc[1][0] - MFIX), q1 = __expf(sc[1][1] - MFIX);
        float q2 = __expf(sc[1][2] - MFIX), q3 = __expf(sc[1][3] - MFIX);
        phj[2] = packtrunc(q0, q1, h0, h1); lr0 += h0 + h1;
        phj[3] = packtrunc(q2, q3, h0, h1); lr1 += h0 + h1;
    }
#pragma unroll
    for (int j2 = 0; j2 < 8; j2++) {
        uint32_t addr = Vst + (uint32_t)(j2 * (16 * 144) + jp * 32) + laneV;
        uint32_t vh_[4], vl_[4];
        LDMX4(vh_, addr);
        LDMX4(vl_, addr + SZ_VHL);
        MMA16816(oacc[2 * j2],     phj, vh_[0], vh_[1]);
        MMA16816(oacc[2 * j2 + 1], phj, vh_[2], vh_[3]);
        MMA16816(oacc[2 * j2],     phj, vl_[0], vl_[1]);
        MMA16816(oacc[2 * j2 + 1], phj, vl_[2], vl_[3]);
    }
}

__global__ void __launch_bounds__(256, 1) flash_kernel()
{
    extern __shared__ char smem[];
    uint32_t sb = smem_to_u32(smem);
    const int tid = threadIdx.x;
    const int w = tid >> 5, lane = tid & 31;
    const int g = lane >> 2, tq = lane & 3;
    const int q0 = blockIdx.x * 128;
    const int split = blockIdx.y;
    const int b = blockIdx.z;
    const int ks = (split * 98) / 3;
    const int ke = ((split + 1) * 98) / 3;

    // prologue: Q (hi/lo) + stage0 in group0; stage1 in group1
    {
        const char* gqh = (const char*)(g_qh + ((size_t)b * NPOS + q0) * D_);
        const char* gql = (const char*)(g_ql + ((size_t)b * NPOS + q0) * D_);
#pragma unroll
        for (int i = 0; i < 8; i++) {
            int ch = tid + i * 256;
            int r = ch >> 4, c = ch & 15;
            uint32_t dst = (uint32_t)(r * 272 + c * 16);
            size_t src = (size_t)r * 256 + c * 16;
            cpa16(sb + dst, gqh + src);
            cpa16(sb + SZ_Q + dst, gql + src);
        }
    }
    ld_stage(sb, 0, b, ks, tid);
    CP_COMMIT();
    ld_stage(sb, 1, b, ks + 1, tid);
    CP_COMMIT();

    float oacc[16][4];
#pragma unroll
    for (int j = 0; j < 16; j++)
#pragma unroll
        for (int e = 0; e < 4; e++) oacc[j][e] = 0.f;
    float lr0 = 0.f, lr1 = 0.f;

    const int r8 = lane & 7, half = (lane >> 3) & 1, jjo = lane >> 4;
    const uint32_t laneK = (uint32_t)((jjo * 8 + r8) * 272 + half * 16);
    const uint32_t laneV = (uint32_t)((jjo * 8 + r8) * 144 + half * 16);
    const uint32_t qbase = sb + (uint32_t)((w * 16 + half * 8 + r8) * 272 + jjo * 16);

    int st = 0;
    for (int t = ks; t < ke; t++) {
        if (t + 1 < ke) {
            asm volatile("cp.async.wait_group 1;" ::: "memory");
        } else {
            asm volatile("cp.async.wait_group 0;" ::: "memory");
        }
        __syncthreads();

        const uint32_t Kst = sb + OFF_KV + st * SZ_STAGE;
        const uint32_t Vst = Kst + SZ_KST;

        float sA[2][2][4], sB[2][2][4];
        s_pair(sA, Kst, 0, qbase, laneK);
        s_pair(sB, Kst, 1, qbase, laneK);
        sm_pv(sA[0], 0, Vst, laneV, oacc, lr0, lr1);
        sm_pv(sA[1], 1, Vst, laneV, oacc, lr0, lr1);
        sm_pv(sB[0], 2, Vst, laneV, oacc, lr0, lr1);
        sm_pv(sB[1], 3, Vst, laneV, oacc, lr0, lr1);

        __syncthreads();
        if (t + 2 < ke) {
            ld_stage(sb, st, b, t + 2, tid);
            CP_COMMIT();
        }
        st ^= 1;
    }

    lr0 += __shfl_xor_sync(0xffffffffu, lr0, 1);
    lr0 += __shfl_xor_sync(0xffffffffu, lr0, 2);
    lr1 += __shfl_xor_sync(0xffffffffu, lr1, 1);
    lr1 += __shfl_xor_sync(0xffffffffu, lr1, 2);
    if (tq == 0) {
        size_t base = (size_t)b * NPOS + q0 + w * 16;
        g_lp[split][base + g] = lr0;
        g_lp[split][base + g + 8] = lr1;
    }

    float* yd = g_yp[split] + ((size_t)b * NPOS + q0 + w * 16) * D_;
#pragma unroll
    for (int j = 0; j < 16; j++) {
        *(float2*)(yd + (size_t)g * D_ + j * 8 + 2 * tq) = make_float2(oacc[j][0], oacc[j][1]);
        *(float2*)(yd + (size_t)(g + 8) * D_ + j * 8 + 2 * tq) = make_float2(oacc[j][2], oacc[j][3]);
    }
}

// =============================================================================
// Kernel 3 (mma): out[b][c][n] = x + Wz @ (Σ_s y_s / L).  n-tile 64, 2 CTAs/SM.
// =============================================================================
#define EPI_WZH  0
#define EPI_WZL  34816
#define EPI_YH   69632
#define EPI_YL   87040
#define EPI_LINV 104448
#define EPI_SMEM (EPI_LINV + 256)

__global__ void __launch_bounds__(256, 2) epi_kernel(
    const float* __restrict__ Wz, const float* __restrict__ x, float* __restrict__ out)
{
    extern __shared__ char smem[];
    uint32_t sb = smem_to_u32(smem);
    const int tid = threadIdx.x;
    const int w = tid >> 5, lane = tid & 31;
    const int g = lane >> 2, tq = lane & 3;
    const int b = blockIdx.z;
    const int c0 = blockIdx.y * 128;
    const int n0 = blockIdx.x * 64;

    float* linv = (float*)(smem + EPI_LINV);
    if (tid < 64) {
        size_t li = (size_t)b * NPOS + n0 + tid;
        linv[tid] = 1.f / (g_lp[0][li] + g_lp[1][li] + g_lp[2][li]);
    }
    __syncthreads();

    for (int v = tid; v < 128 * 32; v += 256) {
        int r = v >> 5, c = v & 31;
        float4 wv = *(const float4*)(Wz + (size_t)(c0 + r) * D_ + 4 * c);
        uint32_t l0, l1;
        uint32_t h0 = packsplit(wv.x, wv.y, l0);
        uint32_t h1 = packsplit(wv.z, wv.w, l1);
        *(uint2*)(smem + EPI_WZH + r * 272 + c * 8) = make_uint2(h0, h1);
        *(uint2*)(smem + EPI_WZL + r * 272 + c * 8) = make_uint2(l0, l1);
    }
    {
        const float* y0 = g_yp[0] + ((size_t)b * NPOS + n0) * D_;
        const float* y1 = g_yp[1] + ((size_t)b * NPOS + n0) * D_;
        const float* y2 = g_yp[2] + ((size_t)b * NPOS + n0) * D_;
        for (int v = tid; v < 64 * 32; v += 256) {
            int r = v >> 5, c = v & 31;
            size_t o = (size_t)r * D_ + 4 * c;
            float4 a = *(const float4*)(y0 + o);
            float4 bb = *(const float4*)(y1 + o);
            float4 cc = *(const float4*)(y2 + o);
            float s = linv[r];
            float vx = (a.x + bb.x + cc.x) * s;
            float vy = (a.y + bb.y + cc.y) * s;
            float vz = (a.z + bb.z + cc.z) * s;
            float vw = (a.w + bb.w + cc.w) * s;
            uint32_t l0, l1;
            uint32_t h0 = packsplit(vx, vy, l0);
            uint32_t h1 = packsplit(vz, vw, l1);
            *(uint2*)(smem + EPI_YH + r * 272 + c * 8) = make_uint2(h0, h1);
            *(uint2*)(smem + EPI_YL + r * 272 + c * 8) = make_uint2(l0, l1);
        }
    }
    __syncthreads();

    float acc[8][4];
#pragma unroll
    for (int j = 0; j < 8; j++)
#pragma unroll
        for (int e = 0; e < 4; e++) acc[j][e] = 0.f;

    const int r8 = lane & 7;
    const uint32_t laneA = (uint32_t)((((lane >> 3) & 1) * 8 + r8) * 272 + (lane >> 4) * 16);
    const uint32_t laneB = (uint32_t)(((lane >> 4) * 8 + r8) * 272 + ((lane >> 3) & 1) * 16);
    const uint32_t wA = sb + EPI_WZH + (uint32_t)(w * 16 * 272);

#pragma unroll
    for (int kk = 0; kk < 8; kk++) {
        uint32_t ah[4], al[4];
        LDMX4(ah, wA + kk * 32 + laneA);
        LDMX4(al, wA + (EPI_WZL - EPI_WZH) + kk * 32 + laneA);
#pragma unroll
        for (int jp = 0; jp < 4; jp++) {
            uint32_t ba = sb + EPI_YH + (uint32_t)(jp * (16 * 272) + kk * 32) + laneB;
            uint32_t bh[4], bl[4];
            LDMX4(bh, ba);
            LDMX4(bl, ba + (EPI_YL - EPI_YH));
            MMA16816(acc[2 * jp],     ah, bh[0], bh[1]);
            MMA16816(acc[2 * jp + 1], ah, bh[2], bh[3]);
            MMA16816(acc[2 * jp],     al, bh[0], bh[1]);
            MMA16816(acc[2 * jp + 1], al, bh[2], bh[3]);
            MMA16816(acc[2 * jp],     ah, bl[0], bl[1]);
            MMA16816(acc[2 * jp + 1], ah, bl[2], bl[3]);
        }
    }

    const size_t row0 = (size_t)(b * C_ + c0 + w * 16 + g) * NPOS + n0;
    const size_t row1 = row0 + (size_t)8 * NPOS;
#pragma unroll
    for (int j = 0; j < 8; j++) {
        int col = j * 8 + 2 * tq;
        float2 x0 = *(const float2*)(x + row0 + col);
        float2 x1 = *(const float2*)(x + row1 + col);
        *(float2*)(out + row0 + col) = make_float2(acc[j][0] + x0.x, acc[j][1] + x0.y);
        *(float2*)(out + row1 + col) = make_float2(acc[j][2] + x1.x, acc[j][3] + x1.y);
    }
}

// =============================================================================
extern "C" void kernel_launch(void* const* d_in, const int* in_sizes, int n_in,
                              void* d_out, int out_size)
{
    const float* x      = (const float*)d_in[0];
    const float* Wg     = (const float*)d_in[1];
    const float* Wtheta = (const float*)d_in[2];
    const float* Wphi   = (const float*)d_in[3];
    const float* Wz     = (const float*)d_in[4];
    float* out = (float*)d_out;

    cudaFuncSetAttribute(proj_mma_kernel, cudaFuncAttributeMaxDynamicSharedMemorySize, PROJ_SMEM);
    cudaFuncSetAttribute(flash_kernel, cudaFuncAttributeMaxDynamicSharedMemorySize, FLASH_SMEM);
    cudaFuncSetAttribute(epi_kernel, cudaFuncAttributeMaxDynamicSharedMemorySize, EPI_SMEM);

    split_x_kernel<<<6272, 256>>>(x);
    split_w_kernel<<<dim3(32, 3), 256>>>(Wtheta, Wphi, Wg);
    proj_mma_kernel<<<dim3(NPOS / 128, 3, B_), 256, PROJ_SMEM>>>();
    flash_kernel<<<dim3(NPOS / 128, NSPLIT, B_), 256, FLASH_SMEM>>>();
    epi_kernel<<<dim3(NPOS / 64, C_ / 128, B_), 256, EPI_SMEM>>>(Wz, x, out);
}